// round 1
// baseline (speedup 1.0000x reference)
#include <cuda_runtime.h>
#include <math.h>

// Problem constants (NiNoModel): N=50000 nodes, E=400000 edges
#define NN   50000
#define EE   400000
#define HIDN 128
#define EAK  45      // MF*CTX = 9*5
#define OUTK 360     // MF*SEQ = 9*40
#define NL   3

// ---- scratch (device globals; no allocation allowed) ----
__device__ __align__(16) float g_x   [(size_t)NN * HIDN];        // node features
__device__ __align__(16) float g_e   [(size_t)EE * HIDN];        // edge features
__device__ __align__(16) float g_np  [(size_t)NN * 4 * HIDN];    // node projections: [a1,a2,p1,p2]
__device__ __align__(16) float g_agg [(size_t)NN * HIDN];        // message aggregation
__device__              float g_invdeg[NN];

__device__ __forceinline__ float siluf(float v) {
    return v * (1.0f / (1.0f + __expf(-v)));
}

// ---------------------------------------------------------------------------
__global__ void k_zero_invdeg(int Ntot) {
    int i = blockIdx.x * blockDim.x + threadIdx.x;
    if (i < Ntot) g_invdeg[i] = 0.0f;
}

__global__ void k_count_deg(const int* __restrict__ ei, int Etot) {
    int i = blockIdx.x * blockDim.x + threadIdx.x;
    if (i < Etot) atomicAdd(&g_invdeg[ei[Etot + i]], 1.0f);  // dst row
}

__global__ void k_fin_invdeg(int Ntot) {
    int i = blockIdx.x * blockDim.x + threadIdx.x;
    if (i < Ntot) g_invdeg[i] = 1.0f / fmaxf(g_invdeg[i], 1.0f);
}

__global__ void k_zero_agg(int Ntot) {
    int i = blockIdx.x * blockDim.x + threadIdx.x;
    if (i < Ntot * HIDN) g_agg[i] = 0.0f;
}

// ---------------------------------------------------------------------------
// x = wte[pos_w] + pos @ node_W^T + node_b          [N,128], LPE=8
__global__ void k_node_init(const float* __restrict__ pos,
                            const int*   __restrict__ pos_w,
                            const float* __restrict__ wte,
                            const float* __restrict__ nW,
                            const float* __restrict__ nb, int Ntot) {
    int n = blockIdx.x;
    if (n >= Ntot) return;
    int j = threadIdx.x;
    __shared__ float s_pos[8];
    if (j < 8) s_pos[j] = pos[(size_t)n * 8 + j];
    __syncthreads();
    float acc = nb[j] + wte[(size_t)pos_w[n] * HIDN + j];
#pragma unroll
    for (int k = 0; k < 8; k++) acc += s_pos[k] * nW[j * 8 + k];
    g_x[(size_t)n * HIDN + j] = acc;
}

// ---------------------------------------------------------------------------
// e = layer_embed[edge_type] + edge_attr @ edge_W^T + edge_b    [E,128], K=45
__global__ void k_edge_init(const float* __restrict__ ea,
                            const int*   __restrict__ et,
                            const float* __restrict__ lemb,
                            const float* __restrict__ eW,
                            const float* __restrict__ eb, int Etot) {
    int e0 = blockIdx.x * 16;
    int j  = threadIdx.x;
    __shared__ float s_a[16][48];
    __shared__ int   s_t[16];
    int nv = min(16, Etot - e0);
    for (int idx = j; idx < nv * EAK; idx += 128) {
        int t = idx / EAK, k = idx % EAK;
        s_a[t][k] = ea[(size_t)(e0 + t) * EAK + k];
    }
    if (j < nv) s_t[j] = et[e0 + j];
    __syncthreads();

    float w[EAK];
#pragma unroll
    for (int k = 0; k < EAK; k++) w[k] = eW[j * EAK + k];
    float ebj = eb[j];

    for (int t = 0; t < nv; t++) {
        float acc = 0.0f;
#pragma unroll
        for (int k = 0; k < EAK; k++) acc += s_a[t][k] * w[k];
        g_e[(size_t)(e0 + t) * HIDN + j] =
            lemb[(size_t)s_t[t] * HIDN + j] + acc + ebj;
    }
}

// ---------------------------------------------------------------------------
// Per-node projections for layer l:
//   np[n][0:128]   = x[n] @ We[:,  0:128]^T   (src part of edge-update)
//   np[n][128:256] = x[n] @ We[:,128:256]^T   (dst part)
//   np[n][256:384] = x[n] @ Wpre[:,  0:128]^T (src part of message)
//   np[n][384:512] = x[n] @ Wpre[:,128:256]^T (dst part)
__global__ void k_node_pre(const float* __restrict__ We,
                           const float* __restrict__ Wpre, int Ntot) {
    int n0 = blockIdx.x * 16;
    int j  = threadIdx.x;
    __shared__ __align__(16) float s_x[16][HIDN];
    int nv = min(16, Ntot - n0);
    for (int t = 0; t < 16; t++)
        s_x[t][j] = (t < nv) ? g_x[(size_t)(n0 + t) * HIDN + j] : 0.0f;
    __syncthreads();

    const float* Ws[4] = { We  + (size_t)j * 384,
                           We  + (size_t)j * 384 + 128,
                           Wpre + (size_t)j * 384,
                           Wpre + (size_t)j * 384 + 128 };
#pragma unroll
    for (int w = 0; w < 4; w++) {
        const float4* wr = (const float4*)Ws[w];
        float acc[16];
#pragma unroll
        for (int t = 0; t < 16; t++) acc[t] = 0.0f;
#pragma unroll 8
        for (int k = 0; k < 32; k++) {
            float4 wv = wr[k];
#pragma unroll
            for (int t = 0; t < 16; t++) {
                float4 xv = ((const float4*)s_x[t])[k];
                acc[t] += xv.x * wv.x + xv.y * wv.y + xv.z * wv.z + xv.w * wv.w;
            }
        }
        for (int t = 0; t < nv; t++)
            g_np[(size_t)(n0 + t) * 512 + w * HIDN + j] = acc[t];
    }
}

// ---------------------------------------------------------------------------
// Edge layer: e' = silu(a1[src] + a2[dst] + e @ We3^T + be)
//             m  = silu(p1[src] + p2[dst] + e' @ Wpre3^T + bpre)
//             agg[dst] += m
__global__ void k_edge_layer(const int* __restrict__ ei,
                             const float* __restrict__ We,
                             const float* __restrict__ be,
                             const float* __restrict__ Wpre,
                             const float* __restrict__ bpre, int Etot) {
    int e0 = blockIdx.x * 16;
    int j  = threadIdx.x;
    __shared__ __align__(16) float s_e[16][HIDN];
    __shared__ int s_src[16], s_dst[16];
    int nv = min(16, Etot - e0);
    if (j < 16) {
        int valid = (j < nv);
        s_src[j] = valid ? ei[e0 + j]         : 0;
        s_dst[j] = valid ? ei[Etot + e0 + j]  : 0;
    }
    for (int t = 0; t < 16; t++)
        s_e[t][j] = (t < nv) ? g_e[(size_t)(e0 + t) * HIDN + j] : 0.0f;
    __syncthreads();

    // ---- phase 1: edge update ----
    float acc[16];
    {
        float bj = be[j];
#pragma unroll
        for (int t = 0; t < 16; t++)
            acc[t] = bj + g_np[(size_t)s_src[t] * 512 + j]
                        + g_np[(size_t)s_dst[t] * 512 + 128 + j];
        const float4* wr = (const float4*)(We + (size_t)j * 384 + 256);
#pragma unroll 8
        for (int k = 0; k < 32; k++) {
            float4 wv = wr[k];
#pragma unroll
            for (int t = 0; t < 16; t++) {
                float4 ev = ((const float4*)s_e[t])[k];
                acc[t] += ev.x * wv.x + ev.y * wv.y + ev.z * wv.z + ev.w * wv.w;
            }
        }
    }
    __syncthreads();   // everyone done reading old e
#pragma unroll
    for (int t = 0; t < 16; t++) {
        float v = siluf(acc[t]);
        if (t < nv) g_e[(size_t)(e0 + t) * HIDN + j] = v;
        s_e[t][j] = v;
    }
    __syncthreads();

    // ---- phase 2: message + scatter ----
    {
        float bj = bpre[j];
#pragma unroll
        for (int t = 0; t < 16; t++)
            acc[t] = bj + g_np[(size_t)s_src[t] * 512 + 256 + j]
                        + g_np[(size_t)s_dst[t] * 512 + 384 + j];
        const float4* wr = (const float4*)(Wpre + (size_t)j * 384 + 256);
#pragma unroll 8
        for (int k = 0; k < 32; k++) {
            float4 wv = wr[k];
#pragma unroll
            for (int t = 0; t < 16; t++) {
                float4 ev = ((const float4*)s_e[t])[k];
                acc[t] += ev.x * wv.x + ev.y * wv.y + ev.z * wv.z + ev.w * wv.w;
            }
        }
        for (int t = 0; t < nv; t++)
            atomicAdd(&g_agg[(size_t)s_dst[t] * HIDN + j], siluf(acc[t]));
    }
}

// ---------------------------------------------------------------------------
// x' = cat([x, agg/deg]) @ Wpost^T + bpost  (silu except last layer)
__global__ void k_node_post(const float* __restrict__ Wpost,
                            const float* __restrict__ bpost,
                            int do_silu, int Ntot) {
    int n0 = blockIdx.x * 16;
    int j  = threadIdx.x;
    __shared__ __align__(16) float s_in[16][256];
    int nv = min(16, Ntot - n0);
    for (int t = 0; t < 16; t++) {
        if (t < nv) {
            float inv = g_invdeg[n0 + t];
            s_in[t][j]        = g_x[(size_t)(n0 + t) * HIDN + j];
            s_in[t][HIDN + j] = g_agg[(size_t)(n0 + t) * HIDN + j] * inv;
        } else {
            s_in[t][j] = 0.0f; s_in[t][HIDN + j] = 0.0f;
        }
    }
    __syncthreads();

    float acc[16];
    float bj = bpost[j];
#pragma unroll
    for (int t = 0; t < 16; t++) acc[t] = bj;
    const float4* wr = (const float4*)(Wpost + (size_t)j * 256);
#pragma unroll 8
    for (int k = 0; k < 64; k++) {
        float4 wv = wr[k];
#pragma unroll
        for (int t = 0; t < 16; t++) {
            float4 iv = ((const float4*)s_in[t])[k];
            acc[t] += iv.x * wv.x + iv.y * wv.y + iv.z * wv.z + iv.w * wv.w;
        }
    }
    for (int t = 0; t < nv; t++) {
        float v = acc[t];
        g_x[(size_t)(n0 + t) * HIDN + j] = do_silu ? siluf(v) : v;
    }
}

// ---------------------------------------------------------------------------
__global__ void k_copy_x(float* __restrict__ out, int Ntot) {
    int i = blockIdx.x * blockDim.x + threadIdx.x;
    if (i < Ntot * HIDN) out[i] = g_x[i];
}

// ---------------------------------------------------------------------------
// Readout: h = silu(e @ W1^T + b1); out = h @ W2^T + b2 + res  (res = last-ctx)
__global__ void k_readout(const float* __restrict__ ea,
                          const float* __restrict__ W1,
                          const float* __restrict__ b1,
                          const float* __restrict__ W2,
                          const float* __restrict__ b2,
                          float* __restrict__ out, int Etot) {
    int e0 = blockIdx.x * 16;
    int j  = threadIdx.x;
    __shared__ __align__(16) float s_e[16][HIDN];
    int nv = min(16, Etot - e0);
    for (int t = 0; t < 16; t++)
        s_e[t][j] = (t < nv) ? g_e[(size_t)(e0 + t) * HIDN + j] : 0.0f;
    __syncthreads();

    // phase 1: hidden
    float acc[16];
    {
        float bj = b1[j];
#pragma unroll
        for (int t = 0; t < 16; t++) acc[t] = bj;
        const float4* wr = (const float4*)(W1 + (size_t)j * HIDN);
#pragma unroll 8
        for (int k = 0; k < 32; k++) {
            float4 wv = wr[k];
#pragma unroll
            for (int t = 0; t < 16; t++) {
                float4 ev = ((const float4*)s_e[t])[k];
                acc[t] += ev.x * wv.x + ev.y * wv.y + ev.z * wv.z + ev.w * wv.w;
            }
        }
    }
    __syncthreads();
#pragma unroll
    for (int t = 0; t < 16; t++) s_e[t][j] = siluf(acc[t]);
    __syncthreads();

    // phase 2: 360 outputs, thread j covers o = j, j+128, j+256
    for (int o = j; o < OUTK; o += 128) {
        float bo = b2[o];
        float a2[16];
#pragma unroll
        for (int t = 0; t < 16; t++) a2[t] = bo;
        const float4* wr = (const float4*)(W2 + (size_t)o * HIDN);
#pragma unroll 8
        for (int k = 0; k < 32; k++) {
            float4 wv = wr[k];
#pragma unroll
            for (int t = 0; t < 16; t++) {
                float4 hv = ((const float4*)s_e[t])[k];
                a2[t] += hv.x * wv.x + hv.y * wv.y + hv.z * wv.z + hv.w * wv.w;
            }
        }
        int mf = o / 40;                      // SEQ = 40
        for (int t = 0; t < nv; t++) {
            float res = ea[(size_t)(e0 + t) * EAK + mf * 5 + 4];  // CTX-1 = 4
            out[(size_t)(e0 + t) * OUTK + o] = a2[t] + res;
        }
    }
}

// ===========================================================================
extern "C" void kernel_launch(void* const* d_in, const int* in_sizes, int n_in,
                              void* d_out, int out_size) {
    const float* edge_attr   = (const float*)d_in[0];
    const int*   edge_type   = (const int*)  d_in[1];
    const float* pos         = (const float*)d_in[2];
    const int*   pos_w       = (const int*)  d_in[3];
    const int*   edge_index  = (const int*)  d_in[4];
    const float* layer_embed = (const float*)d_in[5];
    const float* wte         = (const float*)d_in[6];
    const float* node_W      = (const float*)d_in[7];
    const float* node_b      = (const float*)d_in[8];
    const float* edge_W      = (const float*)d_in[9];
    const float* edge_b      = (const float*)d_in[10];
    const float* gnn_We      = (const float*)d_in[11];
    const float* gnn_be      = (const float*)d_in[12];
    const float* gnn_Wpre    = (const float*)d_in[13];
    const float* gnn_bpre    = (const float*)d_in[14];
    const float* gnn_Wpost   = (const float*)d_in[15];
    const float* gnn_bpost   = (const float*)d_in[16];
    const float* out_W1      = (const float*)d_in[17];
    const float* out_b1      = (const float*)d_in[18];
    const float* out_W2      = (const float*)d_in[19];
    const float* out_b2      = (const float*)d_in[20];

    int E = in_sizes[1];           // edge_type element count
    int N = in_sizes[3];           // pos_w element count
    if (E > EE) E = EE;
    if (N > NN) N = NN;

    float* outp = (float*)d_out;
    float* out_x = nullptr; float* out_o = nullptr;
    long xsz = (long)N * HIDN, osz = (long)E * OUTK;
    if ((long)out_size >= xsz + osz)      { out_x = outp; out_o = outp + xsz; }
    else if ((long)out_size == osz)       { out_o = outp; }
    else                                  { out_x = outp; }

    int EB = (E + 15) / 16, NB = (N + 15) / 16;

    k_zero_invdeg<<<(N + 255) / 256, 256>>>(N);
    k_count_deg  <<<(E + 255) / 256, 256>>>(edge_index, E);
    k_fin_invdeg <<<(N + 255) / 256, 256>>>(N);

    k_node_init<<<N, 128>>>(pos, pos_w, wte, node_W, node_b, N);
    k_edge_init<<<EB, 128>>>(edge_attr, edge_type, layer_embed, edge_W, edge_b, E);

    for (int l = 0; l < NL; l++) {
        k_zero_agg<<<((long)N * HIDN + 255) / 256, 256>>>(N);
        k_node_pre<<<NB, 128>>>(gnn_We + (size_t)l * HIDN * 384,
                                gnn_Wpre + (size_t)l * HIDN * 384, N);
        k_edge_layer<<<EB, 128>>>(edge_index,
                                  gnn_We  + (size_t)l * HIDN * 384, gnn_be  + l * HIDN,
                                  gnn_Wpre + (size_t)l * HIDN * 384, gnn_bpre + l * HIDN, E);
        k_node_post<<<NB, 128>>>(gnn_Wpost + (size_t)l * HIDN * 256,
                                 gnn_bpost + l * HIDN, (l < NL - 1) ? 1 : 0, N);
    }

    if (out_x) k_copy_x<<<((long)N * HIDN + 255) / 256, 256>>>(out_x, N);
    if (out_o) k_readout<<<EB, 128>>>(edge_attr, out_W1, out_b1, out_W2, out_b2, out_o, E);
}

// round 2
// speedup vs baseline: 1.4446x; 1.4446x over previous
#include <cuda_runtime.h>
#include <math.h>

// Problem constants (NiNoModel): N=50000 nodes, E=400000 edges
#define NN   50000
#define EE   400000
#define HIDN 128
#define EAK  45      // MF*CTX = 9*5
#define OUTK 360     // MF*SEQ = 9*40
#define NL   3

typedef unsigned long long u64;

// ---- scratch (device globals; no allocation allowed) ----
__device__ __align__(16) float g_x   [(size_t)NN * HIDN];        // node features
__device__ __align__(16) float g_e   [(size_t)EE * HIDN];        // edge features
__device__ __align__(16) float g_np  [(size_t)NN * 4 * HIDN];    // node projections: [a1,a2,p1,p2]
__device__ __align__(16) float g_agg [(size_t)NN * HIDN];        // message aggregation
__device__              float g_invdeg[NN];

// packed-transposed weights: [K/2 pairs][OUT] of float2 (pair over input dim)
__device__ __align__(16) float2 g_WeS[NL][64][128];   // We src block
__device__ __align__(16) float2 g_WeD[NL][64][128];   // We dst block
__device__ __align__(16) float2 g_WeE[NL][64][128];   // We e   block
__device__ __align__(16) float2 g_WpS[NL][64][128];   // Wpre src
__device__ __align__(16) float2 g_WpD[NL][64][128];   // Wpre dst
__device__ __align__(16) float2 g_WpE[NL][64][128];   // Wpre e
__device__ __align__(16) float2 g_WpoT[NL][128][128]; // Wpost (K=256 -> 128 pairs)
__device__ __align__(16) float2 g_W1T[64][128];
__device__ __align__(16) float2 g_W2T[64][OUTK];
__device__ __align__(16) float2 g_eWT[23][128];       // edge_W (K=45 -> 23 pairs, padded)

__device__ __forceinline__ float siluf(float v) {
    return v * (1.0f / (1.0f + __expf(-v)));
}

// packed f32x2 fma: d = a*b + c (lane-wise on two packed floats)
__device__ __forceinline__ u64 fma2(u64 a, u64 b, u64 c) {
    u64 d;
    asm("fma.rn.f32x2 %0, %1, %2, %3;" : "=l"(d) : "l"(a), "l"(b), "l"(c));
    return d;
}
__device__ __forceinline__ float hadd2(u64 v) {
    float lo, hi;
    asm("mov.b64 {%0, %1}, %2;" : "=f"(lo), "=f"(hi) : "l"(v));
    return lo + hi;
}

// ---------------------------------------------------------------------------
// Pack/transpose all weights into coalesced-friendly layout (runs first).
// seg0: 6 matrices x NL layers of 128x128 blocks from We/Wpre  (147456)
// seg1: Wpost NLx[128][256]                                    ( 49152)
// seg2: W1 [128][128]                                          (  8192)
// seg3: W2 [360][128]                                          ( 23040)
// seg4: edge_W [128][45]                                       (  2944)
__global__ void k_pack_all(const float* __restrict__ We, const float* __restrict__ Wp,
                           const float* __restrict__ Wpo, const float* __restrict__ W1,
                           const float* __restrict__ W2, const float* __restrict__ eW) {
    int i = blockIdx.x * blockDim.x + threadIdx.x;
    if (i < 147456) {
        int j = i % 128, p = (i / 128) % 64, m = (i / 8192) % 6, l = i / 49152;
        const float* src = (m < 3 ? We : Wp) + (size_t)l * 128 * 384;
        int koff = (m % 3) * 128;
        float a = src[(size_t)j * 384 + koff + 2 * p];
        float b = src[(size_t)j * 384 + koff + 2 * p + 1];
        float2 v = make_float2(a, b);
        switch (m) {
            case 0: g_WeS[l][p][j] = v; break;
            case 1: g_WeD[l][p][j] = v; break;
            case 2: g_WeE[l][p][j] = v; break;
            case 3: g_WpS[l][p][j] = v; break;
            case 4: g_WpD[l][p][j] = v; break;
            default: g_WpE[l][p][j] = v; break;
        }
        return;
    }
    i -= 147456;
    if (i < 49152) {
        int j = i % 128, p = (i / 128) % 128, l = i / 16384;
        const float* src = Wpo + (size_t)l * 128 * 256;
        g_WpoT[l][p][j] = make_float2(src[(size_t)j * 256 + 2 * p],
                                      src[(size_t)j * 256 + 2 * p + 1]);
        return;
    }
    i -= 49152;
    if (i < 8192) {
        int j = i % 128, p = i / 128;
        g_W1T[p][j] = make_float2(W1[(size_t)j * 128 + 2 * p],
                                  W1[(size_t)j * 128 + 2 * p + 1]);
        return;
    }
    i -= 8192;
    if (i < 23040) {
        int o = i % OUTK, p = i / OUTK;
        g_W2T[p][o] = make_float2(W2[(size_t)o * 128 + 2 * p],
                                  W2[(size_t)o * 128 + 2 * p + 1]);
        return;
    }
    i -= 23040;
    if (i < 2944) {
        int j = i % 128, p = i / 128;
        float a = eW[(size_t)j * EAK + 2 * p];
        float b = (2 * p + 1 < EAK) ? eW[(size_t)j * EAK + 2 * p + 1] : 0.0f;
        g_eWT[p][j] = make_float2(a, b);
    }
}

// ---------------------------------------------------------------------------
__global__ void k_zero_invdeg(int Ntot) {
    int i = blockIdx.x * blockDim.x + threadIdx.x;
    if (i < Ntot) g_invdeg[i] = 0.0f;
}
__global__ void k_count_deg(const int* __restrict__ ei, int Etot) {
    int i = blockIdx.x * blockDim.x + threadIdx.x;
    if (i < Etot) atomicAdd(&g_invdeg[ei[Etot + i]], 1.0f);
}
__global__ void k_fin_invdeg(int Ntot) {
    int i = blockIdx.x * blockDim.x + threadIdx.x;
    if (i < Ntot) g_invdeg[i] = 1.0f / fmaxf(g_invdeg[i], 1.0f);
}
__global__ void k_zero_agg(int Ntot) {
    int i = blockIdx.x * blockDim.x + threadIdx.x;
    if (i < Ntot * HIDN) g_agg[i] = 0.0f;
}

// ---------------------------------------------------------------------------
// x = wte[pos_w] + pos @ node_W^T + node_b          [N,128], LPE=8
__global__ void k_node_init(const float* __restrict__ pos,
                            const int*   __restrict__ pos_w,
                            const float* __restrict__ wte,
                            const float* __restrict__ nW,
                            const float* __restrict__ nb, int Ntot) {
    int n = blockIdx.x;
    if (n >= Ntot) return;
    int j = threadIdx.x;
    __shared__ float s_pos[8];
    if (j < 8) s_pos[j] = pos[(size_t)n * 8 + j];
    __syncthreads();
    float acc = nb[j] + wte[(size_t)pos_w[n] * HIDN + j];
#pragma unroll
    for (int k = 0; k < 8; k++) acc += s_pos[k] * nW[j * 8 + k];
    g_x[(size_t)n * HIDN + j] = acc;
}

// ---------------------------------------------------------------------------
// e = layer_embed[edge_type] + edge_attr @ edge_W^T + edge_b    [E,128], K=45
__global__ void __launch_bounds__(128) k_edge_init(
        const float* __restrict__ ea, const int* __restrict__ et,
        const float* __restrict__ lemb, const float* __restrict__ eb, int Etot) {
    int e0 = blockIdx.x * 16;
    int j  = threadIdx.x;
    __shared__ __align__(16) float s_a[16][46];
    __shared__ int s_t[16];
    int nv = min(16, Etot - e0);
    for (int idx = j; idx < nv * EAK; idx += 128) {
        int t = idx / EAK, k = idx % EAK;
        s_a[t][k] = ea[(size_t)(e0 + t) * EAK + k];
    }
    if (j < 16) { s_a[j][45] = 0.0f; s_t[j] = (j < nv) ? et[e0 + j] : 0; }
    __syncthreads();

    u64 acc[16];
#pragma unroll
    for (int t = 0; t < 16; t++) acc[t] = 0ull;
    const u64* wp = (const u64*)&g_eWT[0][0];
#pragma unroll
    for (int p = 0; p < 23; p++) {
        u64 w = wp[p * 128 + j];
#pragma unroll
        for (int t = 0; t < 16; t++) {
            u64 av = *(const u64*)&s_a[t][2 * p];
            acc[t] = fma2(av, w, acc[t]);
        }
    }
    float ebj = eb[j];
    for (int t = 0; t < nv; t++)
        g_e[(size_t)(e0 + t) * HIDN + j] =
            lemb[(size_t)s_t[t] * HIDN + j] + hadd2(acc[t]) + ebj;
}

// ---------------------------------------------------------------------------
// Per-node projections: np[n] = [x@WeS^T, x@WeD^T, x@WpS^T, x@WpD^T]
__global__ void __launch_bounds__(128) k_node_pre(int l, int Ntot) {
    int n0 = blockIdx.x * 16;
    int j  = threadIdx.x;
    __shared__ __align__(16) float s_x[16][HIDN];
    int nv = min(16, Ntot - n0);
    for (int t = 0; t < 16; t++)
        s_x[t][j] = (t < nv) ? g_x[(size_t)(n0 + t) * HIDN + j] : 0.0f;
    __syncthreads();

    const u64* WT[4] = { (const u64*)&g_WeS[l][0][0], (const u64*)&g_WeD[l][0][0],
                         (const u64*)&g_WpS[l][0][0], (const u64*)&g_WpD[l][0][0] };
#pragma unroll
    for (int w = 0; w < 4; w++) {
        u64 acc[16];
#pragma unroll
        for (int t = 0; t < 16; t++) acc[t] = 0ull;
        const u64* wp = WT[w];
#pragma unroll 4
        for (int k4 = 0; k4 < 32; k4++) {
            u64 w0 = wp[(2 * k4) * 128 + j];
            u64 w1 = wp[(2 * k4 + 1) * 128 + j];
#pragma unroll
            for (int t = 0; t < 16; t++) {
                ulonglong2 ev = *(const ulonglong2*)&s_x[t][k4 * 4];
                acc[t] = fma2(ev.x, w0, acc[t]);
                acc[t] = fma2(ev.y, w1, acc[t]);
            }
        }
        for (int t = 0; t < nv; t++)
            g_np[(size_t)(n0 + t) * 512 + w * HIDN + j] = hadd2(acc[t]);
    }
}

// ---------------------------------------------------------------------------
// Edge layer: e' = silu(a1[src] + a2[dst] + e @ WeE^T + be)
//             m  = silu(p1[src] + p2[dst] + e' @ WpE^T + bpre);  agg[dst] += m
__global__ void __launch_bounds__(128) k_edge_layer(
        const int* __restrict__ ei,
        const float* __restrict__ be, const float* __restrict__ bpre,
        int l, int Etot) {
    int e0 = blockIdx.x * 16;
    int j  = threadIdx.x;
    __shared__ __align__(16) float s_e[16][HIDN];
    __shared__ int s_src[16], s_dst[16];
    int nv = min(16, Etot - e0);
    if (j < 16) {
        int valid = (j < nv);
        s_src[j] = valid ? ei[e0 + j]        : 0;
        s_dst[j] = valid ? ei[Etot + e0 + j] : 0;
    }
    for (int t = 0; t < 16; t++)
        s_e[t][j] = (t < nv) ? g_e[(size_t)(e0 + t) * HIDN + j] : 0.0f;
    __syncthreads();

    float res[16];

    // ---- phase 1: edge update ----
    {
        u64 acc[16];
#pragma unroll
        for (int t = 0; t < 16; t++) acc[t] = 0ull;
        const u64* wp = (const u64*)&g_WeE[l][0][0];
#pragma unroll 4
        for (int k4 = 0; k4 < 32; k4++) {
            u64 w0 = wp[(2 * k4) * 128 + j];
            u64 w1 = wp[(2 * k4 + 1) * 128 + j];
#pragma unroll
            for (int t = 0; t < 16; t++) {
                ulonglong2 ev = *(const ulonglong2*)&s_e[t][k4 * 4];
                acc[t] = fma2(ev.x, w0, acc[t]);
                acc[t] = fma2(ev.y, w1, acc[t]);
            }
        }
        float bj = be[j];
#pragma unroll
        for (int t = 0; t < 16; t++)
            res[t] = hadd2(acc[t]) + bj
                   + g_np[(size_t)s_src[t] * 512 + j]
                   + g_np[(size_t)s_dst[t] * 512 + 128 + j];
    }
    __syncthreads();   // everyone done reading old e
#pragma unroll
    for (int t = 0; t < 16; t++) {
        float v = siluf(res[t]);
        if (t < nv) g_e[(size_t)(e0 + t) * HIDN + j] = v;
        s_e[t][j] = v;
    }
    __syncthreads();

    // ---- phase 2: message + scatter ----
    {
        u64 acc[16];
#pragma unroll
        for (int t = 0; t < 16; t++) acc[t] = 0ull;
        const u64* wp = (const u64*)&g_WpE[l][0][0];
#pragma unroll 4
        for (int k4 = 0; k4 < 32; k4++) {
            u64 w0 = wp[(2 * k4) * 128 + j];
            u64 w1 = wp[(2 * k4 + 1) * 128 + j];
#pragma unroll
            for (int t = 0; t < 16; t++) {
                ulonglong2 ev = *(const ulonglong2*)&s_e[t][k4 * 4];
                acc[t] = fma2(ev.x, w0, acc[t]);
                acc[t] = fma2(ev.y, w1, acc[t]);
            }
        }
        float bj = bpre[j];
        for (int t = 0; t < nv; t++) {
            float m = siluf(hadd2(acc[t]) + bj
                          + g_np[(size_t)s_src[t] * 512 + 256 + j]
                          + g_np[(size_t)s_dst[t] * 512 + 384 + j]);
            atomicAdd(&g_agg[(size_t)s_dst[t] * HIDN + j], m);
        }
    }
}

// ---------------------------------------------------------------------------
// x' = cat([x, agg/deg]) @ Wpost^T + bpost  (silu except last layer)
__global__ void __launch_bounds__(128) k_node_post(
        const float* __restrict__ bpost, int l, int do_silu, int Ntot) {
    int n0 = blockIdx.x * 16;
    int j  = threadIdx.x;
    __shared__ __align__(16) float s_in[16][256];
    int nv = min(16, Ntot - n0);
    for (int t = 0; t < 16; t++) {
        if (t < nv) {
            float inv = g_invdeg[n0 + t];
            s_in[t][j]        = g_x[(size_t)(n0 + t) * HIDN + j];
            s_in[t][HIDN + j] = g_agg[(size_t)(n0 + t) * HIDN + j] * inv;
        } else {
            s_in[t][j] = 0.0f; s_in[t][HIDN + j] = 0.0f;
        }
    }
    __syncthreads();

    u64 acc[16];
#pragma unroll
    for (int t = 0; t < 16; t++) acc[t] = 0ull;
    const u64* wp = (const u64*)&g_WpoT[l][0][0];
#pragma unroll 4
    for (int k4 = 0; k4 < 64; k4++) {
        u64 w0 = wp[(2 * k4) * 128 + j];
        u64 w1 = wp[(2 * k4 + 1) * 128 + j];
#pragma unroll
        for (int t = 0; t < 16; t++) {
            ulonglong2 iv = *(const ulonglong2*)&s_in[t][k4 * 4];
            acc[t] = fma2(iv.x, w0, acc[t]);
            acc[t] = fma2(iv.y, w1, acc[t]);
        }
    }
    float bj = bpost[j];
    for (int t = 0; t < nv; t++) {
        float v = hadd2(acc[t]) + bj;
        g_x[(size_t)(n0 + t) * HIDN + j] = do_silu ? siluf(v) : v;
    }
}

// ---------------------------------------------------------------------------
__global__ void k_copy_x(float* __restrict__ out, int Ntot) {
    int i = blockIdx.x * blockDim.x + threadIdx.x;
    if (i < Ntot * HIDN) out[i] = g_x[i];
}

// ---------------------------------------------------------------------------
// Readout: h = silu(e @ W1^T + b1); out = h @ W2^T + b2 + res (res = last-ctx)
__global__ void __launch_bounds__(128) k_readout(
        const float* __restrict__ ea,
        const float* __restrict__ b1, const float* __restrict__ b2,
        float* __restrict__ out, int Etot) {
    int e0 = blockIdx.x * 16;
    int j  = threadIdx.x;
    __shared__ __align__(16) float s_e[16][HIDN];
    int nv = min(16, Etot - e0);
    for (int t = 0; t < 16; t++)
        s_e[t][j] = (t < nv) ? g_e[(size_t)(e0 + t) * HIDN + j] : 0.0f;
    __syncthreads();

    // phase 1: hidden
    {
        u64 acc[16];
#pragma unroll
        for (int t = 0; t < 16; t++) acc[t] = 0ull;
        const u64* wp = (const u64*)&g_W1T[0][0];
#pragma unroll 4
        for (int k4 = 0; k4 < 32; k4++) {
            u64 w0 = wp[(2 * k4) * 128 + j];
            u64 w1 = wp[(2 * k4 + 1) * 128 + j];
#pragma unroll
            for (int t = 0; t < 16; t++) {
                ulonglong2 ev = *(const ulonglong2*)&s_e[t][k4 * 4];
                acc[t] = fma2(ev.x, w0, acc[t]);
                acc[t] = fma2(ev.y, w1, acc[t]);
            }
        }
        float bj = b1[j];
        float h[16];
#pragma unroll
        for (int t = 0; t < 16; t++) h[t] = siluf(hadd2(acc[t]) + bj);
        __syncthreads();
#pragma unroll
        for (int t = 0; t < 16; t++) s_e[t][j] = h[t];
        __syncthreads();
    }

    // phase 2: 360 outputs; thread j covers o = j, j+128, (j+256 if j<104)
    {
        bool has3 = (j < OUTK - 256);
        int o2 = has3 ? j + 256 : 0;
        u64 acc[3][16];
#pragma unroll
        for (int r = 0; r < 3; r++)
#pragma unroll
            for (int t = 0; t < 16; t++) acc[r][t] = 0ull;
        const u64* wp = (const u64*)&g_W2T[0][0];
#pragma unroll 2
        for (int k4 = 0; k4 < 32; k4++) {
            u64 wa0 = wp[(2 * k4) * OUTK + j];
            u64 wa1 = wp[(2 * k4 + 1) * OUTK + j];
            u64 wb0 = wp[(2 * k4) * OUTK + j + 128];
            u64 wb1 = wp[(2 * k4 + 1) * OUTK + j + 128];
            u64 wc0 = wp[(2 * k4) * OUTK + o2];
            u64 wc1 = wp[(2 * k4 + 1) * OUTK + o2];
#pragma unroll
            for (int t = 0; t < 16; t++) {
                ulonglong2 hv = *(const ulonglong2*)&s_e[t][k4 * 4];
                acc[0][t] = fma2(hv.x, wa0, acc[0][t]);
                acc[0][t] = fma2(hv.y, wa1, acc[0][t]);
                acc[1][t] = fma2(hv.x, wb0, acc[1][t]);
                acc[1][t] = fma2(hv.y, wb1, acc[1][t]);
                acc[2][t] = fma2(hv.x, wc0, acc[2][t]);
                acc[2][t] = fma2(hv.y, wc1, acc[2][t]);
            }
        }
        int oo[3] = { j, j + 128, o2 };
#pragma unroll
        for (int r = 0; r < 3; r++) {
            if (r == 2 && !has3) break;
            int o = oo[r];
            float bo = b2[o];
            int mf = o / 40;                 // SEQ = 40
            for (int t = 0; t < nv; t++) {
                float res = ea[(size_t)(e0 + t) * EAK + mf * 5 + 4];  // CTX-1 = 4
                out[(size_t)(e0 + t) * OUTK + o] = hadd2(acc[r][t]) + bo + res;
            }
        }
    }
}

// ===========================================================================
extern "C" void kernel_launch(void* const* d_in, const int* in_sizes, int n_in,
                              void* d_out, int out_size) {
    const float* edge_attr   = (const float*)d_in[0];
    const int*   edge_type   = (const int*)  d_in[1];
    const float* pos         = (const float*)d_in[2];
    const int*   pos_w       = (const int*)  d_in[3];
    const int*   edge_index  = (const int*)  d_in[4];
    const float* layer_embed = (const float*)d_in[5];
    const float* wte         = (const float*)d_in[6];
    const float* node_W      = (const float*)d_in[7];
    const float* node_b      = (const float*)d_in[8];
    const float* edge_W      = (const float*)d_in[9];
    const float* edge_b      = (const float*)d_in[10];
    const float* gnn_We      = (const float*)d_in[11];
    const float* gnn_be      = (const float*)d_in[12];
    const float* gnn_Wpre    = (const float*)d_in[13];
    const float* gnn_bpre    = (const float*)d_in[14];
    const float* gnn_Wpost   = (const float*)d_in[15];
    const float* gnn_bpost   = (const float*)d_in[16];
    const float* out_W1      = (const float*)d_in[17];
    const float* out_b1      = (const float*)d_in[18];
    const float* out_W2      = (const float*)d_in[19];
    const float* out_b2      = (const float*)d_in[20];

    int E = in_sizes[1];
    int N = in_sizes[3];
    if (E > EE) E = EE;
    if (N > NN) N = NN;

    float* outp = (float*)d_out;
    float* out_x = nullptr; float* out_o = nullptr;
    long xsz = (long)N * HIDN, osz = (long)E * OUTK;
    if ((long)out_size >= xsz + osz)      { out_x = outp; out_o = outp + xsz; }
    else if ((long)out_size == osz)       { out_o = outp; }
    else                                  { out_x = outp; }

    int EB = (E + 15) / 16, NB = (N + 15) / 16;

    // weight pre-pack (230784 elems)
    k_pack_all<<<(230784 + 255) / 256, 256>>>(gnn_We, gnn_Wpre, gnn_Wpost,
                                              out_W1, out_W2, edge_W);

    k_zero_invdeg<<<(N + 255) / 256, 256>>>(N);
    k_count_deg  <<<(E + 255) / 256, 256>>>(edge_index, E);
    k_fin_invdeg <<<(N + 255) / 256, 256>>>(N);

    k_node_init<<<N, 128>>>(pos, pos_w, wte, node_W, node_b, N);
    k_edge_init<<<EB, 128>>>(edge_attr, edge_type, layer_embed, edge_b, E);

    for (int l = 0; l < NL; l++) {
        k_zero_agg<<<((long)N * HIDN + 255) / 256, 256>>>(N);
        k_node_pre<<<NB, 128>>>(l, N);
        k_edge_layer<<<EB, 128>>>(edge_index, gnn_be + l * HIDN,
                                  gnn_bpre + l * HIDN, l, E);
        k_node_post<<<NB, 128>>>(gnn_bpost + l * HIDN, l, (l < NL - 1) ? 1 : 0, N);
    }

    if (out_x) k_copy_x<<<((long)N * HIDN + 255) / 256, 256>>>(out_x, N);
    if (out_o) k_readout<<<EB, 128>>>(edge_attr, out_b1, out_b2, out_o, E);
}

// round 3
// speedup vs baseline: 1.4503x; 1.0039x over previous
#include <cuda_runtime.h>
#include <math.h>

// Problem constants (NiNoModel): N=50000 nodes, E=400000 edges
#define NN   50000
#define EE   400000
#define HIDN 128
#define EAK  45      // MF*CTX = 9*5
#define OUTK 360     // MF*SEQ = 9*40
#define NL   3

typedef unsigned long long u64;

// ---- scratch (device globals; no allocation allowed) ----
__device__ __align__(16) float g_x   [(size_t)NN * HIDN];
__device__ __align__(16) float g_e   [(size_t)EE * HIDN];
__device__ __align__(16) float g_np  [(size_t)NN * 4 * HIDN];   // [a1,a2,p1,p2]
__device__ __align__(16) float g_agg [(size_t)NN * HIDN];
__device__              float g_deg  [NN];                       // raw degree

// packed-transposed weights: [K/2 pairs][OUT] of float2 (pair over input dim)
__device__ __align__(16) float2 g_WeS[NL][64][128];
__device__ __align__(16) float2 g_WeD[NL][64][128];
__device__ __align__(16) float2 g_WeE[NL][64][128];
__device__ __align__(16) float2 g_WpS[NL][64][128];
__device__ __align__(16) float2 g_WpD[NL][64][128];
__device__ __align__(16) float2 g_WpE[NL][64][128];
__device__ __align__(16) float2 g_WpoT[NL][128][128];
__device__ __align__(16) float2 g_W1T[64][128];
__device__ __align__(16) float2 g_W2T[64][OUTK];
__device__ __align__(16) float2 g_eWT[23][128];

__device__ __forceinline__ float siluf(float v) {
    return v * (1.0f / (1.0f + __expf(-v)));
}
__device__ __forceinline__ u64 fma2(u64 a, u64 b, u64 c) {
    u64 d;
    asm("fma.rn.f32x2 %0, %1, %2, %3;" : "=l"(d) : "l"(a), "l"(b), "l"(c));
    return d;
}
__device__ __forceinline__ float hadd2(u64 v) {
    float lo, hi;
    asm("mov.b64 {%0, %1}, %2;" : "=f"(lo), "=f"(hi) : "l"(v));
    return lo + hi;
}

// ---------------------------------------------------------------------------
__global__ void k_pack_all(const float* __restrict__ We, const float* __restrict__ Wp,
                           const float* __restrict__ Wpo, const float* __restrict__ W1,
                           const float* __restrict__ W2, const float* __restrict__ eW) {
    int i = blockIdx.x * blockDim.x + threadIdx.x;
    if (i < 147456) {
        int j = i % 128, p = (i / 128) % 64, m = (i / 8192) % 6, l = i / 49152;
        const float* src = (m < 3 ? We : Wp) + (size_t)l * 128 * 384;
        int koff = (m % 3) * 128;
        float2 v = make_float2(src[(size_t)j * 384 + koff + 2 * p],
                               src[(size_t)j * 384 + koff + 2 * p + 1]);
        switch (m) {
            case 0: g_WeS[l][p][j] = v; break;
            case 1: g_WeD[l][p][j] = v; break;
            case 2: g_WeE[l][p][j] = v; break;
            case 3: g_WpS[l][p][j] = v; break;
            case 4: g_WpD[l][p][j] = v; break;
            default: g_WpE[l][p][j] = v; break;
        }
        return;
    }
    i -= 147456;
    if (i < 49152) {
        int j = i % 128, p = (i / 128) % 128, l = i / 16384;
        const float* src = Wpo + (size_t)l * 128 * 256;
        g_WpoT[l][p][j] = make_float2(src[(size_t)j * 256 + 2 * p],
                                      src[(size_t)j * 256 + 2 * p + 1]);
        return;
    }
    i -= 49152;
    if (i < 8192) {
        int j = i % 128, p = i / 128;
        g_W1T[p][j] = make_float2(W1[(size_t)j * 128 + 2 * p],
                                  W1[(size_t)j * 128 + 2 * p + 1]);
        return;
    }
    i -= 8192;
    if (i < 23040) {
        int o = i % OUTK, p = i / OUTK;
        g_W2T[p][o] = make_float2(W2[(size_t)o * 128 + 2 * p],
                                  W2[(size_t)o * 128 + 2 * p + 1]);
        return;
    }
    i -= 23040;
    if (i < 2944) {
        int j = i % 128, p = i / 128;
        float a = eW[(size_t)j * EAK + 2 * p];
        float b = (2 * p + 1 < EAK) ? eW[(size_t)j * EAK + 2 * p + 1] : 0.0f;
        g_eWT[p][j] = make_float2(a, b);
    }
}

// ---------------------------------------------------------------------------
__global__ void k_zero_deg_agg(int Ntot) {
    int i = blockIdx.x * blockDim.x + threadIdx.x;
    if (i < Ntot) g_deg[i] = 0.0f;
    if (i < Ntot * HIDN) g_agg[i] = 0.0f;
}
__global__ void k_count_deg(const int* __restrict__ ei, int Etot) {
    int i = blockIdx.x * blockDim.x + threadIdx.x;
    if (i < Etot) atomicAdd(&g_deg[ei[Etot + i]], 1.0f);
}

// ---------------------------------------------------------------------------
// x = wte[pos_w] + pos @ node_W^T + node_b          [N,128], LPE=8
__global__ void k_node_init(const float* __restrict__ pos,
                            const int*   __restrict__ pos_w,
                            const float* __restrict__ wte,
                            const float* __restrict__ nW,
                            const float* __restrict__ nb, int Ntot) {
    int n = blockIdx.x;
    if (n >= Ntot) return;
    int j = threadIdx.x;
    __shared__ float s_pos[8];
    if (j < 8) s_pos[j] = pos[(size_t)n * 8 + j];
    __syncthreads();
    float acc = nb[j] + wte[(size_t)pos_w[n] * HIDN + j];
#pragma unroll
    for (int k = 0; k < 8; k++) acc += s_pos[k] * nW[j * 8 + k];
    g_x[(size_t)n * HIDN + j] = acc;
}

// ---------------------------------------------------------------------------
// e = layer_embed[edge_type] + edge_attr @ edge_W^T + edge_b    [E,128], K=45
__global__ void __launch_bounds__(128) k_edge_init(
        const float* __restrict__ ea, const int* __restrict__ et,
        const float* __restrict__ lemb, const float* __restrict__ eb, int Etot) {
    int e0 = blockIdx.x * 16;
    int j  = threadIdx.x;
    __shared__ __align__(16) float s_a[16][46];
    __shared__ int s_t[16];
    int nv = min(16, Etot - e0);
    for (int idx = j; idx < nv * EAK; idx += 128) {
        int t = idx / EAK, k = idx % EAK;
        s_a[t][k] = ea[(size_t)(e0 + t) * EAK + k];
    }
    if (j < 16) { s_a[j][45] = 0.0f; s_t[j] = (j < nv) ? et[e0 + j] : 0; }
    __syncthreads();

    u64 acc[16];
#pragma unroll
    for (int t = 0; t < 16; t++) acc[t] = 0ull;
    const u64* wp = (const u64*)&g_eWT[0][0];
#pragma unroll
    for (int p = 0; p < 23; p++) {
        u64 w = wp[p * 128 + j];
#pragma unroll
        for (int t = 0; t < 16; t++)
            acc[t] = fma2(*(const u64*)&s_a[t][2 * p], w, acc[t]);
    }
    float ebj = eb[j];
    for (int t = 0; t < nv; t++)
        g_e[(size_t)(e0 + t) * HIDN + j] =
            lemb[(size_t)s_t[t] * HIDN + j] + hadd2(acc[t]) + ebj;
}

// ---------------------------------------------------------------------------
// Per-node projections; 64 threads, each thread covers cols j0 and j0+64.
__global__ void __launch_bounds__(64) k_node_pre(int l, int Ntot) {
    int n0 = blockIdx.x * 16;
    int j0 = threadIdx.x;                 // 0..63
    __shared__ __align__(16) float s_x[16][HIDN];
    int nv = min(16, Ntot - n0);
    for (int t = 0; t < 16; t++) {
        float a = 0.0f, b = 0.0f;
        if (t < nv) {
            a = g_x[(size_t)(n0 + t) * HIDN + j0];
            b = g_x[(size_t)(n0 + t) * HIDN + j0 + 64];
        }
        s_x[t][j0] = a; s_x[t][j0 + 64] = b;
    }
    __syncthreads();

    const u64* WT[4] = { (const u64*)&g_WeS[l][0][0], (const u64*)&g_WeD[l][0][0],
                         (const u64*)&g_WpS[l][0][0], (const u64*)&g_WpD[l][0][0] };
#pragma unroll
    for (int w = 0; w < 4; w++) {
        u64 acc0[16], acc1[16];
#pragma unroll
        for (int t = 0; t < 16; t++) { acc0[t] = 0ull; acc1[t] = 0ull; }
        const u64* wp = WT[w];
#pragma unroll 2
        for (int k4 = 0; k4 < 32; k4++) {
            u64 wA0 = wp[(2 * k4) * 128 + j0];
            u64 wA1 = wp[(2 * k4 + 1) * 128 + j0];
            u64 wB0 = wp[(2 * k4) * 128 + j0 + 64];
            u64 wB1 = wp[(2 * k4 + 1) * 128 + j0 + 64];
#pragma unroll
            for (int t = 0; t < 16; t++) {
                ulonglong2 xv = *(const ulonglong2*)&s_x[t][k4 * 4];
                acc0[t] = fma2(xv.x, wA0, acc0[t]);
                acc0[t] = fma2(xv.y, wA1, acc0[t]);
                acc1[t] = fma2(xv.x, wB0, acc1[t]);
                acc1[t] = fma2(xv.y, wB1, acc1[t]);
            }
        }
        for (int t = 0; t < nv; t++) {
            g_np[(size_t)(n0 + t) * 512 + w * HIDN + j0]      = hadd2(acc0[t]);
            g_np[(size_t)(n0 + t) * 512 + w * HIDN + j0 + 64] = hadd2(acc1[t]);
        }
    }
}

// ---------------------------------------------------------------------------
// Edge layer, 64 threads / 2 cols per thread.
__global__ void __launch_bounds__(64) k_edge_layer(
        const int* __restrict__ ei,
        const float* __restrict__ be, const float* __restrict__ bpre,
        int l, int Etot) {
    int e0 = blockIdx.x * 16;
    int j0 = threadIdx.x;
    __shared__ __align__(16) float s_e[16][HIDN];
    __shared__ int s_src[16], s_dst[16];
    int nv = min(16, Etot - e0);
    if (j0 < 16) {
        int valid = (j0 < nv);
        s_src[j0] = valid ? ei[e0 + j0]        : 0;
        s_dst[j0] = valid ? ei[Etot + e0 + j0] : 0;
    }
    for (int t = 0; t < 16; t++) {
        float a = 0.0f, b = 0.0f;
        if (t < nv) {
            a = g_e[(size_t)(e0 + t) * HIDN + j0];
            b = g_e[(size_t)(e0 + t) * HIDN + j0 + 64];
        }
        s_e[t][j0] = a; s_e[t][j0 + 64] = b;
    }
    __syncthreads();

    float r0[16], r1[16];

    // ---- phase 1: edge update ----
    {
        u64 acc0[16], acc1[16];
#pragma unroll
        for (int t = 0; t < 16; t++) { acc0[t] = 0ull; acc1[t] = 0ull; }
        const u64* wp = (const u64*)&g_WeE[l][0][0];
#pragma unroll 2
        for (int k4 = 0; k4 < 32; k4++) {
            u64 wA0 = wp[(2 * k4) * 128 + j0];
            u64 wA1 = wp[(2 * k4 + 1) * 128 + j0];
            u64 wB0 = wp[(2 * k4) * 128 + j0 + 64];
            u64 wB1 = wp[(2 * k4 + 1) * 128 + j0 + 64];
#pragma unroll
            for (int t = 0; t < 16; t++) {
                ulonglong2 ev = *(const ulonglong2*)&s_e[t][k4 * 4];
                acc0[t] = fma2(ev.x, wA0, acc0[t]);
                acc0[t] = fma2(ev.y, wA1, acc0[t]);
                acc1[t] = fma2(ev.x, wB0, acc1[t]);
                acc1[t] = fma2(ev.y, wB1, acc1[t]);
            }
        }
        float b0 = be[j0], b1 = be[j0 + 64];
#pragma unroll
        for (int t = 0; t < 16; t++) {
            size_t s5 = (size_t)s_src[t] * 512, d5 = (size_t)s_dst[t] * 512;
            r0[t] = hadd2(acc0[t]) + b0 + g_np[s5 + j0]      + g_np[d5 + 128 + j0];
            r1[t] = hadd2(acc1[t]) + b1 + g_np[s5 + j0 + 64] + g_np[d5 + 192 + j0];
        }
    }
    __syncthreads();
#pragma unroll
    for (int t = 0; t < 16; t++) {
        float v0 = siluf(r0[t]), v1 = siluf(r1[t]);
        if (t < nv) {
            g_e[(size_t)(e0 + t) * HIDN + j0]      = v0;
            g_e[(size_t)(e0 + t) * HIDN + j0 + 64] = v1;
        }
        s_e[t][j0] = v0; s_e[t][j0 + 64] = v1;
    }
    __syncthreads();

    // ---- phase 2: message + scatter ----
    {
        u64 acc0[16], acc1[16];
#pragma unroll
        for (int t = 0; t < 16; t++) { acc0[t] = 0ull; acc1[t] = 0ull; }
        const u64* wp = (const u64*)&g_WpE[l][0][0];
#pragma unroll 2
        for (int k4 = 0; k4 < 32; k4++) {
            u64 wA0 = wp[(2 * k4) * 128 + j0];
            u64 wA1 = wp[(2 * k4 + 1) * 128 + j0];
            u64 wB0 = wp[(2 * k4) * 128 + j0 + 64];
            u64 wB1 = wp[(2 * k4 + 1) * 128 + j0 + 64];
#pragma unroll
            for (int t = 0; t < 16; t++) {
                ulonglong2 ev = *(const ulonglong2*)&s_e[t][k4 * 4];
                acc0[t] = fma2(ev.x, wA0, acc0[t]);
                acc0[t] = fma2(ev.y, wA1, acc0[t]);
                acc1[t] = fma2(ev.x, wB0, acc1[t]);
                acc1[t] = fma2(ev.y, wB1, acc1[t]);
            }
        }
        float b0 = bpre[j0], b1 = bpre[j0 + 64];
        for (int t = 0; t < nv; t++) {
            size_t s5 = (size_t)s_src[t] * 512, d5 = (size_t)s_dst[t] * 512;
            float m0 = siluf(hadd2(acc0[t]) + b0 + g_np[s5 + 256 + j0] + g_np[d5 + 384 + j0]);
            float m1 = siluf(hadd2(acc1[t]) + b1 + g_np[s5 + 320 + j0] + g_np[d5 + 448 + j0]);
            atomicAdd(&g_agg[(size_t)s_dst[t] * HIDN + j0],      m0);
            atomicAdd(&g_agg[(size_t)s_dst[t] * HIDN + j0 + 64], m1);
        }
    }
}

// ---------------------------------------------------------------------------
// x' = cat([x, agg/deg]) @ Wpost^T + bpost; also zeroes g_agg for next layer.
__global__ void __launch_bounds__(64) k_node_post(
        const float* __restrict__ bpost, int l, int do_silu, int Ntot) {
    int n0 = blockIdx.x * 16;
    int j0 = threadIdx.x;
    __shared__ __align__(16) float s_in[16][256];
    int nv = min(16, Ntot - n0);
    for (int t = 0; t < 16; t++) {
        float a = 0.f, b = 0.f, c = 0.f, d = 0.f;
        if (t < nv) {
            float inv = 1.0f / fmaxf(g_deg[n0 + t], 1.0f);
            size_t base = (size_t)(n0 + t) * HIDN;
            a = g_x[base + j0];
            b = g_x[base + j0 + 64];
            c = g_agg[base + j0] * inv;
            d = g_agg[base + j0 + 64] * inv;
            g_agg[base + j0] = 0.0f;        // zero for next layer
            g_agg[base + j0 + 64] = 0.0f;
        }
        s_in[t][j0] = a; s_in[t][j0 + 64] = b;
        s_in[t][128 + j0] = c; s_in[t][192 + j0] = d;
    }
    __syncthreads();

    u64 acc0[16], acc1[16];
#pragma unroll
    for (int t = 0; t < 16; t++) { acc0[t] = 0ull; acc1[t] = 0ull; }
    const u64* wp = (const u64*)&g_WpoT[l][0][0];
#pragma unroll 2
    for (int k4 = 0; k4 < 64; k4++) {
        u64 wA0 = wp[(2 * k4) * 128 + j0];
        u64 wA1 = wp[(2 * k4 + 1) * 128 + j0];
        u64 wB0 = wp[(2 * k4) * 128 + j0 + 64];
        u64 wB1 = wp[(2 * k4 + 1) * 128 + j0 + 64];
#pragma unroll
        for (int t = 0; t < 16; t++) {
            ulonglong2 iv = *(const ulonglong2*)&s_in[t][k4 * 4];
            acc0[t] = fma2(iv.x, wA0, acc0[t]);
            acc0[t] = fma2(iv.y, wA1, acc0[t]);
            acc1[t] = fma2(iv.x, wB0, acc1[t]);
            acc1[t] = fma2(iv.y, wB1, acc1[t]);
        }
    }
    float b0 = bpost[j0], b1 = bpost[j0 + 64];
    for (int t = 0; t < nv; t++) {
        float v0 = hadd2(acc0[t]) + b0;
        float v1 = hadd2(acc1[t]) + b1;
        size_t base = (size_t)(n0 + t) * HIDN;
        g_x[base + j0]      = do_silu ? siluf(v0) : v0;
        g_x[base + j0 + 64] = do_silu ? siluf(v1) : v1;
    }
}

// ---------------------------------------------------------------------------
__global__ void k_copy_x(float* __restrict__ out, int Ntot) {
    int i = blockIdx.x * blockDim.x + threadIdx.x;
    if (i < Ntot * HIDN) out[i] = g_x[i];
}

// ---------------------------------------------------------------------------
// Readout, 64 threads: h = silu(e@W1^T + b1); out = h@W2^T + b2 + res
__global__ void __launch_bounds__(64) k_readout(
        const float* __restrict__ ea,
        const float* __restrict__ b1, const float* __restrict__ b2,
        float* __restrict__ out, int Etot) {
    int e0 = blockIdx.x * 16;
    int j0 = threadIdx.x;
    __shared__ __align__(16) float s_e[16][HIDN];
    int nv = min(16, Etot - e0);
    for (int t = 0; t < 16; t++) {
        float a = 0.f, b = 0.f;
        if (t < nv) {
            a = g_e[(size_t)(e0 + t) * HIDN + j0];
            b = g_e[(size_t)(e0 + t) * HIDN + j0 + 64];
        }
        s_e[t][j0] = a; s_e[t][j0 + 64] = b;
    }
    __syncthreads();

    // phase 1: hidden layer (128 outputs, 2 cols/thread)
    {
        u64 acc0[16], acc1[16];
#pragma unroll
        for (int t = 0; t < 16; t++) { acc0[t] = 0ull; acc1[t] = 0ull; }
        const u64* wp = (const u64*)&g_W1T[0][0];
#pragma unroll 2
        for (int k4 = 0; k4 < 32; k4++) {
            u64 wA0 = wp[(2 * k4) * 128 + j0];
            u64 wA1 = wp[(2 * k4 + 1) * 128 + j0];
            u64 wB0 = wp[(2 * k4) * 128 + j0 + 64];
            u64 wB1 = wp[(2 * k4 + 1) * 128 + j0 + 64];
#pragma unroll
            for (int t = 0; t < 16; t++) {
                ulonglong2 ev = *(const ulonglong2*)&s_e[t][k4 * 4];
                acc0[t] = fma2(ev.x, wA0, acc0[t]);
                acc0[t] = fma2(ev.y, wA1, acc0[t]);
                acc1[t] = fma2(ev.x, wB0, acc1[t]);
                acc1[t] = fma2(ev.y, wB1, acc1[t]);
            }
        }
        float bb0 = b1[j0], bb1 = b1[j0 + 64];
        float h0[16], h1[16];
#pragma unroll
        for (int t = 0; t < 16; t++) {
            h0[t] = siluf(hadd2(acc0[t]) + bb0);
            h1[t] = siluf(hadd2(acc1[t]) + bb1);
        }
        __syncthreads();
#pragma unroll
        for (int t = 0; t < 16; t++) { s_e[t][j0] = h0[t]; s_e[t][j0 + 64] = h1[t]; }
        __syncthreads();
    }

    // phase 2: 360 outputs in 3 passes of 2 cols (last pass 2nd col partial)
#pragma unroll 1
    for (int r = 0; r < 3; r++) {
        int cA = j0 + 128 * r;
        int cB = j0 + 64 + 128 * r;
        bool hasB = (cB < OUTK);
        int cBs = hasB ? cB : 0;
        u64 acc0[16], acc1[16];
#pragma unroll
        for (int t = 0; t < 16; t++) { acc0[t] = 0ull; acc1[t] = 0ull; }
        const u64* wp = (const u64*)&g_W2T[0][0];
#pragma unroll 2
        for (int k4 = 0; k4 < 32; k4++) {
            u64 wA0 = wp[(2 * k4) * OUTK + cA];
            u64 wA1 = wp[(2 * k4 + 1) * OUTK + cA];
            u64 wB0 = wp[(2 * k4) * OUTK + cBs];
            u64 wB1 = wp[(2 * k4 + 1) * OUTK + cBs];
#pragma unroll
            for (int t = 0; t < 16; t++) {
                ulonglong2 hv = *(const ulonglong2*)&s_e[t][k4 * 4];
                acc0[t] = fma2(hv.x, wA0, acc0[t]);
                acc0[t] = fma2(hv.y, wA1, acc0[t]);
                acc1[t] = fma2(hv.x, wB0, acc1[t]);
                acc1[t] = fma2(hv.y, wB1, acc1[t]);
            }
        }
        float bA = b2[cA], bB = b2[cBs];
        int mfA = cA / 40, mfB = cBs / 40;       // SEQ = 40
        for (int t = 0; t < nv; t++) {
            const float* ear = ea + (size_t)(e0 + t) * EAK;
            float* orow = out + (size_t)(e0 + t) * OUTK;
            orow[cA] = hadd2(acc0[t]) + bA + ear[mfA * 5 + 4];
            if (hasB) orow[cB] = hadd2(acc1[t]) + bB + ear[mfB * 5 + 4];
        }
    }
}

// ===========================================================================
extern "C" void kernel_launch(void* const* d_in, const int* in_sizes, int n_in,
                              void* d_out, int out_size) {
    const float* edge_attr   = (const float*)d_in[0];
    const int*   edge_type   = (const int*)  d_in[1];
    const float* pos         = (const float*)d_in[2];
    const int*   pos_w       = (const int*)  d_in[3];
    const int*   edge_index  = (const int*)  d_in[4];
    const float* layer_embed = (const float*)d_in[5];
    const float* wte         = (const float*)d_in[6];
    const float* node_W      = (const float*)d_in[7];
    const float* node_b      = (const float*)d_in[8];
    const float* edge_W      = (const float*)d_in[9];
    const float* edge_b      = (const float*)d_in[10];
    const float* gnn_We      = (const float*)d_in[11];
    const float* gnn_be      = (const float*)d_in[12];
    const float* gnn_Wpre    = (const float*)d_in[13];
    const float* gnn_bpre    = (const float*)d_in[14];
    const float* gnn_Wpost   = (const float*)d_in[15];
    const float* gnn_bpost   = (const float*)d_in[16];
    const float* out_W1      = (const float*)d_in[17];
    const float* out_b1      = (const float*)d_in[18];
    const float* out_W2      = (const float*)d_in[19];
    const float* out_b2      = (const float*)d_in[20];

    int E = in_sizes[1];
    int N = in_sizes[3];
    if (E > EE) E = EE;
    if (N > NN) N = NN;

    float* outp = (float*)d_out;
    float* out_x = nullptr; float* out_o = nullptr;
    long xsz = (long)N * HIDN, osz = (long)E * OUTK;
    if ((long)out_size >= xsz + osz)      { out_x = outp; out_o = outp + xsz; }
    else if ((long)out_size == osz)       { out_o = outp; }
    else                                  { out_x = outp; }

    int EB = (E + 15) / 16, NB = (N + 15) / 16;

    // launches ordered so #4 (the profiled one) is k_node_pre (heavy GEMM)
    k_pack_all<<<(230784 + 255) / 256, 256>>>(gnn_We, gnn_Wpre, gnn_Wpost,
                                              out_W1, out_W2, edge_W);          // 1
    k_node_init<<<N, 128>>>(pos, pos_w, wte, node_W, node_b, N);                // 2
    k_edge_init<<<EB, 128>>>(edge_attr, edge_type, layer_embed, edge_b, E);     // 3
    k_node_pre<<<NB, 64>>>(0, N);                                               // 4 (profiled)
    k_zero_deg_agg<<<((long)N * HIDN + 255) / 256, 256>>>(N);                   // 5
    k_count_deg<<<(E + 255) / 256, 256>>>(edge_index, E);                       // 6

    for (int l = 0; l < NL; l++) {
        if (l > 0) k_node_pre<<<NB, 64>>>(l, N);
        k_edge_layer<<<EB, 64>>>(edge_index, gnn_be + l * HIDN,
                                 gnn_bpre + l * HIDN, l, E);
        k_node_post<<<NB, 64>>>(gnn_bpost + l * HIDN, l, (l < NL - 1) ? 1 : 0, N);
    }

    if (out_x) k_copy_x<<<((long)N * HIDN + 255) / 256, 256>>>(out_x, N);
    if (out_o) k_readout<<<EB, 64>>>(edge_attr, out_b1, out_b2, out_o, E);
}

// round 4
// speedup vs baseline: 1.4647x; 1.0099x over previous
#include <cuda_runtime.h>
#include <math.h>

// Problem constants (NiNoModel): N=50000 nodes, E=400000 edges
#define NN   50000
#define EE   400000
#define HIDN 128
#define EAK  45      // MF*CTX = 9*5
#define OUTK 360     // MF*SEQ = 9*40
#define NL   3

typedef unsigned long long u64;

// ---- scratch (device globals; no allocation allowed) ----
__device__ __align__(16) float g_x   [(size_t)NN * HIDN];
__device__ __align__(16) float g_e   [(size_t)EE * HIDN];
__device__ __align__(16) float g_np  [(size_t)NN * 4 * HIDN];   // [a1,a2,p1,p2]
__device__ __align__(16) float g_agg [(size_t)NN * HIDN];
__device__              float g_deg  [NN];                       // raw degree

// packed-transposed weights: [K/2 pairs][OUT] of float2 (pair over input dim)
__device__ __align__(16) float2 g_WeS[NL][64][128];
__device__ __align__(16) float2 g_WeD[NL][64][128];
__device__ __align__(16) float2 g_WeE[NL][64][128];
__device__ __align__(16) float2 g_WpS[NL][64][128];
__device__ __align__(16) float2 g_WpD[NL][64][128];
__device__ __align__(16) float2 g_WpE[NL][64][128];
__device__ __align__(16) float2 g_WpoT[NL][128][128];
__device__ __align__(16) float2 g_W1T[64][128];
__device__ __align__(16) float2 g_W2T[64][OUTK];
__device__ __align__(16) float2 g_eWT[23][128];

__device__ __forceinline__ float siluf(float v) {
    return v * (1.0f / (1.0f + __expf(-v)));
}
__device__ __forceinline__ u64 fma2(u64 a, u64 b, u64 c) {
    u64 d;
    asm("fma.rn.f32x2 %0, %1, %2, %3;" : "=l"(d) : "l"(a), "l"(b), "l"(c));
    return d;
}
__device__ __forceinline__ float hadd2(u64 v) {
    float lo, hi;
    asm("mov.b64 {%0, %1}, %2;" : "=f"(lo), "=f"(hi) : "l"(v));
    return lo + hi;
}

// ---------------------------------------------------------------------------
__global__ void k_pack_all(const float* __restrict__ We, const float* __restrict__ Wp,
                           const float* __restrict__ Wpo, const float* __restrict__ W1,
                           const float* __restrict__ W2, const float* __restrict__ eW) {
    int i = blockIdx.x * blockDim.x + threadIdx.x;
    if (i < 147456) {
        int j = i % 128, p = (i / 128) % 64, m = (i / 8192) % 6, l = i / 49152;
        const float* src = (m < 3 ? We : Wp) + (size_t)l * 128 * 384;
        int koff = (m % 3) * 128;
        float2 v = make_float2(src[(size_t)j * 384 + koff + 2 * p],
                               src[(size_t)j * 384 + koff + 2 * p + 1]);
        switch (m) {
            case 0: g_WeS[l][p][j] = v; break;
            case 1: g_WeD[l][p][j] = v; break;
            case 2: g_WeE[l][p][j] = v; break;
            case 3: g_WpS[l][p][j] = v; break;
            case 4: g_WpD[l][p][j] = v; break;
            default: g_WpE[l][p][j] = v; break;
        }
        return;
    }
    i -= 147456;
    if (i < 49152) {
        int j = i % 128, p = (i / 128) % 128, l = i / 16384;
        const float* src = Wpo + (size_t)l * 128 * 256;
        g_WpoT[l][p][j] = make_float2(src[(size_t)j * 256 + 2 * p],
                                      src[(size_t)j * 256 + 2 * p + 1]);
        return;
    }
    i -= 49152;
    if (i < 8192) {
        int j = i % 128, p = i / 128;
        g_W1T[p][j] = make_float2(W1[(size_t)j * 128 + 2 * p],
                                  W1[(size_t)j * 128 + 2 * p + 1]);
        return;
    }
    i -= 8192;
    if (i < 23040) {
        int o = i % OUTK, p = i / OUTK;
        g_W2T[p][o] = make_float2(W2[(size_t)o * 128 + 2 * p],
                                  W2[(size_t)o * 128 + 2 * p + 1]);
        return;
    }
    i -= 23040;
    if (i < 2944) {
        int j = i % 128, p = i / 128;
        float a = eW[(size_t)j * EAK + 2 * p];
        float b = (2 * p + 1 < EAK) ? eW[(size_t)j * EAK + 2 * p + 1] : 0.0f;
        g_eWT[p][j] = make_float2(a, b);
    }
}

// ---------------------------------------------------------------------------
__global__ void k_zero_deg_agg(int Ntot) {
    int i = blockIdx.x * blockDim.x + threadIdx.x;
    if (i < Ntot) g_deg[i] = 0.0f;
    if (i < Ntot * HIDN) g_agg[i] = 0.0f;
}
__global__ void k_count_deg(const int* __restrict__ ei, int Etot) {
    int i = blockIdx.x * blockDim.x + threadIdx.x;
    if (i < Etot) atomicAdd(&g_deg[ei[Etot + i]], 1.0f);
}

// ---------------------------------------------------------------------------
// x = wte[pos_w] + pos @ node_W^T + node_b          [N,128], LPE=8
__global__ void k_node_init(const float* __restrict__ pos,
                            const int*   __restrict__ pos_w,
                            const float* __restrict__ wte,
                            const float* __restrict__ nW,
                            const float* __restrict__ nb, int Ntot) {
    int n = blockIdx.x;
    if (n >= Ntot) return;
    int j = threadIdx.x;
    __shared__ float s_pos[8];
    if (j < 8) s_pos[j] = pos[(size_t)n * 8 + j];
    __syncthreads();
    float acc = nb[j] + wte[(size_t)pos_w[n] * HIDN + j];
#pragma unroll
    for (int k = 0; k < 8; k++) acc += s_pos[k] * nW[j * 8 + k];
    g_x[(size_t)n * HIDN + j] = acc;
}

// ---------------------------------------------------------------------------
// e = layer_embed[edge_type] + edge_attr @ edge_W^T + edge_b    [E,128], K=45
__global__ void __launch_bounds__(128) k_edge_init(
        const float* __restrict__ ea, const int* __restrict__ et,
        const float* __restrict__ lemb, const float* __restrict__ eb, int Etot) {
    int e0 = blockIdx.x * 16;
    int j  = threadIdx.x;
    __shared__ __align__(16) float s_a[16][46];
    __shared__ int s_t[16];
    int nv = min(16, Etot - e0);
    for (int idx = j; idx < nv * EAK; idx += 128) {
        int t = idx / EAK, k = idx % EAK;
        s_a[t][k] = ea[(size_t)(e0 + t) * EAK + k];
    }
    if (j < 16) { s_a[j][45] = 0.0f; s_t[j] = (j < nv) ? et[e0 + j] : 0; }
    __syncthreads();

    u64 acc[16];
#pragma unroll
    for (int t = 0; t < 16; t++) acc[t] = 0ull;
    const u64* wp = (const u64*)&g_eWT[0][0];
#pragma unroll
    for (int p = 0; p < 23; p++) {
        u64 w = wp[p * 128 + j];
#pragma unroll
        for (int t = 0; t < 16; t++)
            acc[t] = fma2(*(const u64*)&s_a[t][2 * p], w, acc[t]);
    }
    float ebj = eb[j];
    for (int t = 0; t < nv; t++)
        g_e[(size_t)(e0 + t) * HIDN + j] =
            lemb[(size_t)s_t[t] * HIDN + j] + hadd2(acc[t]) + ebj;
}

// ---------------------------------------------------------------------------
// Per-node projections; 64 threads, each thread covers cols j0 and j0+64.
__global__ void __launch_bounds__(64) k_node_pre(int l, int Ntot) {
    int n0 = blockIdx.x * 16;
    int j0 = threadIdx.x;                 // 0..63
    __shared__ __align__(16) float s_x[16][HIDN];
    int nv = min(16, Ntot - n0);
    for (int t = 0; t < 16; t++) {
        float a = 0.0f, b = 0.0f;
        if (t < nv) {
            a = g_x[(size_t)(n0 + t) * HIDN + j0];
            b = g_x[(size_t)(n0 + t) * HIDN + j0 + 64];
        }
        s_x[t][j0] = a; s_x[t][j0 + 64] = b;
    }
    __syncthreads();

    const u64* WT[4] = { (const u64*)&g_WeS[l][0][0], (const u64*)&g_WeD[l][0][0],
                         (const u64*)&g_WpS[l][0][0], (const u64*)&g_WpD[l][0][0] };
#pragma unroll
    for (int w = 0; w < 4; w++) {
        u64 acc0[16], acc1[16];
#pragma unroll
        for (int t = 0; t < 16; t++) { acc0[t] = 0ull; acc1[t] = 0ull; }
        const u64* wp = WT[w];
#pragma unroll 2
        for (int k4 = 0; k4 < 32; k4++) {
            u64 wA0 = wp[(2 * k4) * 128 + j0];
            u64 wA1 = wp[(2 * k4 + 1) * 128 + j0];
            u64 wB0 = wp[(2 * k4) * 128 + j0 + 64];
            u64 wB1 = wp[(2 * k4 + 1) * 128 + j0 + 64];
#pragma unroll
            for (int t = 0; t < 16; t++) {
                ulonglong2 xv = *(const ulonglong2*)&s_x[t][k4 * 4];
                acc0[t] = fma2(xv.x, wA0, acc0[t]);
                acc0[t] = fma2(xv.y, wA1, acc0[t]);
                acc1[t] = fma2(xv.x, wB0, acc1[t]);
                acc1[t] = fma2(xv.y, wB1, acc1[t]);
            }
        }
        for (int t = 0; t < nv; t++) {
            g_np[(size_t)(n0 + t) * 512 + w * HIDN + j0]      = hadd2(acc0[t]);
            g_np[(size_t)(n0 + t) * 512 + w * HIDN + j0 + 64] = hadd2(acc1[t]);
        }
    }
}

// ---------------------------------------------------------------------------
// Edge layer, 64 threads / 2 cols per thread.
__global__ void __launch_bounds__(64) k_edge_layer(
        const int* __restrict__ ei,
        const float* __restrict__ be, const float* __restrict__ bpre,
        int l, int Etot) {
    int e0 = blockIdx.x * 16;
    int j0 = threadIdx.x;
    __shared__ __align__(16) float s_e[16][HIDN];
    __shared__ int s_src[16], s_dst[16];
    int nv = min(16, Etot - e0);
    if (j0 < 16) {
        int valid = (j0 < nv);
        s_src[j0] = valid ? ei[e0 + j0]        : 0;
        s_dst[j0] = valid ? ei[Etot + e0 + j0] : 0;
    }
    for (int t = 0; t < 16; t++) {
        float a = 0.0f, b = 0.0f;
        if (t < nv) {
            a = g_e[(size_t)(e0 + t) * HIDN + j0];
            b = g_e[(size_t)(e0 + t) * HIDN + j0 + 64];
        }
        s_e[t][j0] = a; s_e[t][j0 + 64] = b;
    }
    __syncthreads();

    float r0[16], r1[16];

    // ---- phase 1: edge update ----
    {
        u64 acc0[16], acc1[16];
#pragma unroll
        for (int t = 0; t < 16; t++) { acc0[t] = 0ull; acc1[t] = 0ull; }
        const u64* wp = (const u64*)&g_WeE[l][0][0];
#pragma unroll 2
        for (int k4 = 0; k4 < 32; k4++) {
            u64 wA0 = wp[(2 * k4) * 128 + j0];
            u64 wA1 = wp[(2 * k4 + 1) * 128 + j0];
            u64 wB0 = wp[(2 * k4) * 128 + j0 + 64];
            u64 wB1 = wp[(2 * k4 + 1) * 128 + j0 + 64];
#pragma unroll
            for (int t = 0; t < 16; t++) {
                ulonglong2 ev = *(const ulonglong2*)&s_e[t][k4 * 4];
                acc0[t] = fma2(ev.x, wA0, acc0[t]);
                acc0[t] = fma2(ev.y, wA1, acc0[t]);
                acc1[t] = fma2(ev.x, wB0, acc1[t]);
                acc1[t] = fma2(ev.y, wB1, acc1[t]);
            }
        }
        float b0 = be[j0], b1 = be[j0 + 64];
#pragma unroll
        for (int t = 0; t < 16; t++) {
            size_t s5 = (size_t)s_src[t] * 512, d5 = (size_t)s_dst[t] * 512;
            r0[t] = hadd2(acc0[t]) + b0 + g_np[s5 + j0]      + g_np[d5 + 128 + j0];
            r1[t] = hadd2(acc1[t]) + b1 + g_np[s5 + j0 + 64] + g_np[d5 + 192 + j0];
        }
    }
    __syncthreads();
#pragma unroll
    for (int t = 0; t < 16; t++) {
        float v0 = siluf(r0[t]), v1 = siluf(r1[t]);
        if (t < nv) {
            g_e[(size_t)(e0 + t) * HIDN + j0]      = v0;
            g_e[(size_t)(e0 + t) * HIDN + j0 + 64] = v1;
        }
        s_e[t][j0] = v0; s_e[t][j0 + 64] = v1;
    }
    __syncthreads();

    // ---- phase 2: message + scatter ----
    {
        u64 acc0[16], acc1[16];
#pragma unroll
        for (int t = 0; t < 16; t++) { acc0[t] = 0ull; acc1[t] = 0ull; }
        const u64* wp = (const u64*)&g_WpE[l][0][0];
#pragma unroll 2
        for (int k4 = 0; k4 < 32; k4++) {
            u64 wA0 = wp[(2 * k4) * 128 + j0];
            u64 wA1 = wp[(2 * k4 + 1) * 128 + j0];
            u64 wB0 = wp[(2 * k4) * 128 + j0 + 64];
            u64 wB1 = wp[(2 * k4 + 1) * 128 + j0 + 64];
#pragma unroll
            for (int t = 0; t < 16; t++) {
                ulonglong2 ev = *(const ulonglong2*)&s_e[t][k4 * 4];
                acc0[t] = fma2(ev.x, wA0, acc0[t]);
                acc0[t] = fma2(ev.y, wA1, acc0[t]);
                acc1[t] = fma2(ev.x, wB0, acc1[t]);
                acc1[t] = fma2(ev.y, wB1, acc1[t]);
            }
        }
        float b0 = bpre[j0], b1 = bpre[j0 + 64];
        for (int t = 0; t < nv; t++) {
            size_t s5 = (size_t)s_src[t] * 512, d5 = (size_t)s_dst[t] * 512;
            float m0 = siluf(hadd2(acc0[t]) + b0 + g_np[s5 + 256 + j0] + g_np[d5 + 384 + j0]);
            float m1 = siluf(hadd2(acc1[t]) + b1 + g_np[s5 + 320 + j0] + g_np[d5 + 448 + j0]);
            atomicAdd(&g_agg[(size_t)s_dst[t] * HIDN + j0],      m0);
            atomicAdd(&g_agg[(size_t)s_dst[t] * HIDN + j0 + 64], m1);
        }
    }
}

// ---------------------------------------------------------------------------
// x' = cat([x, agg/deg]) @ Wpost^T + bpost; also zeroes g_agg for next layer.
__global__ void __launch_bounds__(64) k_node_post(
        const float* __restrict__ bpost, int l, int do_silu, int Ntot) {
    int n0 = blockIdx.x * 16;
    int j0 = threadIdx.x;
    __shared__ __align__(16) float s_in[16][256];
    int nv = min(16, Ntot - n0);
    for (int t = 0; t < 16; t++) {
        float a = 0.f, b = 0.f, c = 0.f, d = 0.f;
        if (t < nv) {
            float inv = 1.0f / fmaxf(g_deg[n0 + t], 1.0f);
            size_t base = (size_t)(n0 + t) * HIDN;
            a = g_x[base + j0];
            b = g_x[base + j0 + 64];
            c = g_agg[base + j0] * inv;
            d = g_agg[base + j0 + 64] * inv;
            g_agg[base + j0] = 0.0f;        // zero for next layer
            g_agg[base + j0 + 64] = 0.0f;
        }
        s_in[t][j0] = a; s_in[t][j0 + 64] = b;
        s_in[t][128 + j0] = c; s_in[t][192 + j0] = d;
    }
    __syncthreads();

    u64 acc0[16], acc1[16];
#pragma unroll
    for (int t = 0; t < 16; t++) { acc0[t] = 0ull; acc1[t] = 0ull; }
    const u64* wp = (const u64*)&g_WpoT[l][0][0];
#pragma unroll 2
    for (int k4 = 0; k4 < 64; k4++) {
        u64 wA0 = wp[(2 * k4) * 128 + j0];
        u64 wA1 = wp[(2 * k4 + 1) * 128 + j0];
        u64 wB0 = wp[(2 * k4) * 128 + j0 + 64];
        u64 wB1 = wp[(2 * k4 + 1) * 128 + j0 + 64];
#pragma unroll
        for (int t = 0; t < 16; t++) {
            ulonglong2 iv = *(const ulonglong2*)&s_in[t][k4 * 4];
            acc0[t] = fma2(iv.x, wA0, acc0[t]);
            acc0[t] = fma2(iv.y, wA1, acc0[t]);
            acc1[t] = fma2(iv.x, wB0, acc1[t]);
            acc1[t] = fma2(iv.y, wB1, acc1[t]);
        }
    }
    float b0 = bpost[j0], b1 = bpost[j0 + 64];
    for (int t = 0; t < nv; t++) {
        float v0 = hadd2(acc0[t]) + b0;
        float v1 = hadd2(acc1[t]) + b1;
        size_t base = (size_t)(n0 + t) * HIDN;
        g_x[base + j0]      = do_silu ? siluf(v0) : v0;
        g_x[base + j0 + 64] = do_silu ? siluf(v1) : v1;
    }
}

// ---------------------------------------------------------------------------
__global__ void k_copy_x(float* __restrict__ out, int Ntot) {
    int i = blockIdx.x * blockDim.x + threadIdx.x;
    if (i < Ntot * HIDN) out[i] = g_x[i];
}

// ---------------------------------------------------------------------------
// Readout, 64 threads: h = silu(e@W1^T + b1); out = h@W2^T + b2 + res
__global__ void __launch_bounds__(64) k_readout(
        const float* __restrict__ ea,
        const float* __restrict__ b1, const float* __restrict__ b2,
        float* __restrict__ out, int Etot) {
    int e0 = blockIdx.x * 16;
    int j0 = threadIdx.x;
    __shared__ __align__(16) float s_e[16][HIDN];
    int nv = min(16, Etot - e0);
    for (int t = 0; t < 16; t++) {
        float a = 0.f, b = 0.f;
        if (t < nv) {
            a = g_e[(size_t)(e0 + t) * HIDN + j0];
            b = g_e[(size_t)(e0 + t) * HIDN + j0 + 64];
        }
        s_e[t][j0] = a; s_e[t][j0 + 64] = b;
    }
    __syncthreads();

    // phase 1: hidden layer (128 outputs, 2 cols/thread)
    {
        u64 acc0[16], acc1[16];
#pragma unroll
        for (int t = 0; t < 16; t++) { acc0[t] = 0ull; acc1[t] = 0ull; }
        const u64* wp = (const u64*)&g_W1T[0][0];
#pragma unroll 2
        for (int k4 = 0; k4 < 32; k4++) {
            u64 wA0 = wp[(2 * k4) * 128 + j0];
            u64 wA1 = wp[(2 * k4 + 1) * 128 + j0];
            u64 wB0 = wp[(2 * k4) * 128 + j0 + 64];
            u64 wB1 = wp[(2 * k4 + 1) * 128 + j0 + 64];
#pragma unroll
            for (int t = 0; t < 16; t++) {
                ulonglong2 ev = *(const ulonglong2*)&s_e[t][k4 * 4];
                acc0[t] = fma2(ev.x, wA0, acc0[t]);
                acc0[t] = fma2(ev.y, wA1, acc0[t]);
                acc1[t] = fma2(ev.x, wB0, acc1[t]);
                acc1[t] = fma2(ev.y, wB1, acc1[t]);
            }
        }
        float bb0 = b1[j0], bb1 = b1[j0 + 64];
        float h0[16], h1[16];
#pragma unroll
        for (int t = 0; t < 16; t++) {
            h0[t] = siluf(hadd2(acc0[t]) + bb0);
            h1[t] = siluf(hadd2(acc1[t]) + bb1);
        }
        __syncthreads();
#pragma unroll
        for (int t = 0; t < 16; t++) { s_e[t][j0] = h0[t]; s_e[t][j0 + 64] = h1[t]; }
        __syncthreads();
    }

    // phase 2: 360 outputs in 3 passes of 2 cols (last pass 2nd col partial)
#pragma unroll 1
    for (int r = 0; r < 3; r++) {
        int cA = j0 + 128 * r;
        int cB = j0 + 64 + 128 * r;
        bool hasB = (cB < OUTK);
        int cBs = hasB ? cB : 0;
        u64 acc0[16], acc1[16];
#pragma unroll
        for (int t = 0; t < 16; t++) { acc0[t] = 0ull; acc1[t] = 0ull; }
        const u64* wp = (const u64*)&g_W2T[0][0];
#pragma unroll 2
        for (int k4 = 0; k4 < 32; k4++) {
            u64 wA0 = wp[(2 * k4) * OUTK + cA];
            u64 wA1 = wp[(2 * k4 + 1) * OUTK + cA];
            u64 wB0 = wp[(2 * k4) * OUTK + cBs];
            u64 wB1 = wp[(2 * k4 + 1) * OUTK + cBs];
#pragma unroll
            for (int t = 0; t < 16; t++) {
                ulonglong2 hv = *(const ulonglong2*)&s_e[t][k4 * 4];
                acc0[t] = fma2(hv.x, wA0, acc0[t]);
                acc0[t] = fma2(hv.y, wA1, acc0[t]);
                acc1[t] = fma2(hv.x, wB0, acc1[t]);
                acc1[t] = fma2(hv.y, wB1, acc1[t]);
            }
        }
        float bA = b2[cA], bB = b2[cBs];
        int mfA = cA / 40, mfB = cBs / 40;       // SEQ = 40
        for (int t = 0; t < nv; t++) {
            const float* ear = ea + (size_t)(e0 + t) * EAK;
            float* orow = out + (size_t)(e0 + t) * OUTK;
            orow[cA] = hadd2(acc0[t]) + bA + ear[mfA * 5 + 4];
            if (hasB) orow[cB] = hadd2(acc1[t]) + bB + ear[mfB * 5 + 4];
        }
    }
}

// ===========================================================================
extern "C" void kernel_launch(void* const* d_in, const int* in_sizes, int n_in,
                              void* d_out, int out_size) {
    const float* edge_attr   = (const float*)d_in[0];
    const int*   edge_type   = (const int*)  d_in[1];
    const float* pos         = (const float*)d_in[2];
    const int*   pos_w       = (const int*)  d_in[3];
    const int*   edge_index  = (const int*)  d_in[4];
    const float* layer_embed = (const float*)d_in[5];
    const float* wte         = (const float*)d_in[6];
    const float* node_W      = (const float*)d_in[7];
    const float* node_b      = (const float*)d_in[8];
    const float* edge_W      = (const float*)d_in[9];
    const float* edge_b      = (const float*)d_in[10];
    const float* gnn_We      = (const float*)d_in[11];
    const float* gnn_be      = (const float*)d_in[12];
    const float* gnn_Wpre    = (const float*)d_in[13];
    const float* gnn_bpre    = (const float*)d_in[14];
    const float* gnn_Wpost   = (const float*)d_in[15];
    const float* gnn_bpost   = (const float*)d_in[16];
    const float* out_W1      = (const float*)d_in[17];
    const float* out_b1      = (const float*)d_in[18];
    const float* out_W2      = (const float*)d_in[19];
    const float* out_b2      = (const float*)d_in[20];

    int E = in_sizes[1];
    int N = in_sizes[3];
    if (E > EE) E = EE;
    if (N > NN) N = NN;

    float* outp = (float*)d_out;
    float* out_x = nullptr; float* out_o = nullptr;
    long xsz = (long)N * HIDN, osz = (long)E * OUTK;
    if ((long)out_size >= xsz + osz)      { out_x = outp; out_o = outp + xsz; }
    else if ((long)out_size == osz)       { out_o = outp; }
    else                                  { out_x = outp; }

    int EB = (E + 15) / 16, NB = (N + 15) / 16;

    // launches ordered so #4 (the profiled one) is k_node_pre (heavy GEMM)
    k_pack_all<<<(230784 + 255) / 256, 256>>>(gnn_We, gnn_Wpre, gnn_Wpost,
                                              out_W1, out_W2, edge_W);          // 1
    k_node_init<<<N, 128>>>(pos, pos_w, wte, node_W, node_b, N);                // 2
    k_edge_init<<<EB, 128>>>(edge_attr, edge_type, layer_embed, edge_b, E);     // 3
    k_node_pre<<<NB, 64>>>(0, N);                                               // 4 (profiled)
    k_zero_deg_agg<<<((long)N * HIDN + 255) / 256, 256>>>(N);                   // 5
    k_count_deg<<<(E + 255) / 256, 256>>>(edge_index, E);                       // 6

    for (int l = 0; l < NL; l++) {
        if (l > 0) k_node_pre<<<NB, 64>>>(l, N);
        k_edge_layer<<<EB, 64>>>(edge_index, gnn_be + l * HIDN,
                                 gnn_bpre + l * HIDN, l, E);
        k_node_post<<<NB, 64>>>(gnn_bpost + l * HIDN, l, (l < NL - 1) ? 1 : 0, N);
    }

    if (out_x) k_copy_x<<<((long)N * HIDN + 255) / 256, 256>>>(out_x, N);
    if (out_o) k_readout<<<EB, 64>>>(edge_attr, out_b1, out_b2, out_o, E);
}

// round 6
// speedup vs baseline: 1.7881x; 1.2208x over previous
#include <cuda_runtime.h>
#include <math.h>
#include <stdint.h>

#define NN   50000
#define EE   400000
#define HIDN 128
#define EAK  45
#define OUTK 360
#define NL   3

typedef unsigned long long u64;

// ---- scratch ----
__device__ __align__(16) float g_x   [(size_t)NN * HIDN];
__device__ __align__(16) float g_e   [(size_t)EE * HIDN];
__device__ __align__(16) float g_np  [(size_t)NN * 4 * HIDN];
__device__ __align__(16) float g_agg [(size_t)NN * HIDN];   // zero between layers (node_post restores)
__device__              float g_deg  [NN];

// scalar packed weights (node-side kernels)
__device__ __align__(16) float2 g_WeS[NL][64][128];
__device__ __align__(16) float2 g_WeD[NL][64][128];
__device__ __align__(16) float2 g_WpS[NL][64][128];
__device__ __align__(16) float2 g_WpD[NL][64][128];
__device__ __align__(16) float2 g_WpoT[NL][128][128];
__device__ __align__(16) float2 g_eWT[23][128];

// tensor B images: [k(128)][n stride 136] tf32 bits.
// 0..2 WeE[l], 3..5 WpE[l], 6 W1, 7..9 W2 col-chunks (zero padded)
#define IMG_ELEMS 17408     // 128*136
__device__ __align__(16) uint32_t g_img[10][IMG_ELEMS];

__device__ __forceinline__ float siluf(float v) {
    return v * (1.0f / (1.0f + __expf(-v)));
}
__device__ __forceinline__ u64 fma2(u64 a, u64 b, u64 c) {
    u64 d;
    asm("fma.rn.f32x2 %0, %1, %2, %3;" : "=l"(d) : "l"(a), "l"(b), "l"(c));
    return d;
}
__device__ __forceinline__ float hadd2(u64 v) {
    float lo, hi;
    asm("mov.b64 {%0, %1}, %2;" : "=f"(lo), "=f"(hi) : "l"(v));
    return lo + hi;
}
__device__ __forceinline__ uint32_t f2t(float v) {
    uint32_t o;
    asm("cvt.rna.tf32.f32 %0, %1;" : "=r"(o) : "f"(v));
    return o;
}

// ===================== warp-level tf32 MMA =====================
__device__ __forceinline__ void mma1688(float d[4], const uint32_t a[4],
                                        uint32_t b0, uint32_t b1) {
    asm volatile(
        "mma.sync.aligned.m16n8k8.row.col.f32.tf32.tf32.f32 "
        "{%0,%1,%2,%3}, {%4,%5,%6,%7}, {%8,%9}, {%0,%1,%2,%3};\n"
        : "+f"(d[0]), "+f"(d[1]), "+f"(d[2]), "+f"(d[3])
        : "r"(a[0]), "r"(a[1]), "r"(a[2]), "r"(a[3]), "r"(b0), "r"(b1));
}

#define SA_STR 132
#define SB_STR 136

// warp computes rows [RO, RO+32) x cols [CO, CO+64), k = 128
__device__ __forceinline__ void gemm_warp(const uint32_t* __restrict__ sA,
                                          const uint32_t* __restrict__ sB,
                                          int RO, int CO, int lane,
                                          float acc[2][8][4]) {
    int lr = lane >> 2, lc = lane & 3;
#pragma unroll 4
    for (int k = 0; k < 128; k += 8) {
        uint32_t a[2][4];
#pragma unroll
        for (int rt = 0; rt < 2; rt++) {
            int rb = RO + 16 * rt;
            a[rt][0] = sA[(rb + lr) * SA_STR + k + lc];
            a[rt][1] = sA[(rb + lr + 8) * SA_STR + k + lc];
            a[rt][2] = sA[(rb + lr) * SA_STR + k + 4 + lc];
            a[rt][3] = sA[(rb + lr + 8) * SA_STR + k + 4 + lc];
        }
#pragma unroll
        for (int ct = 0; ct < 8; ct++) {
            uint32_t b0 = sB[(k + lc) * SB_STR + CO + 8 * ct + lr];
            uint32_t b1 = sB[(k + 4 + lc) * SB_STR + CO + 8 * ct + lr];
            mma1688(acc[0][ct], a[0], b0, b1);
            mma1688(acc[1][ct], a[1], b0, b1);
        }
    }
}
__device__ __forceinline__ void zero_acc(float acc[2][8][4]) {
#pragma unroll
    for (int i = 0; i < 2; i++)
#pragma unroll
        for (int j = 0; j < 8; j++)
#pragma unroll
            for (int q = 0; q < 4; q++) acc[i][j][q] = 0.0f;
}

// ---------------------------------------------------------------------------
// pack: scalar packs + tensor images + deg zero
__global__ void k_pack_all(const float* __restrict__ We, const float* __restrict__ Wp,
                           const float* __restrict__ Wpo, const float* __restrict__ W1,
                           const float* __restrict__ W2, const float* __restrict__ eW,
                           int Ntot) {
    int i = blockIdx.x * blockDim.x + threadIdx.x;
    if (i < 98304) {   // WeS/WeD/WpS/WpD
        int j = i % 128, p = (i / 128) % 64, m = (i / 8192) % 4, l = i / 32768;
        const float* src = (m < 2 ? We : Wp) + (size_t)l * 128 * 384;
        int koff = (m & 1) * 128;
        float2 v = make_float2(src[(size_t)j * 384 + koff + 2 * p],
                               src[(size_t)j * 384 + koff + 2 * p + 1]);
        switch (m) {
            case 0: g_WeS[l][p][j] = v; break;
            case 1: g_WeD[l][p][j] = v; break;
            case 2: g_WpS[l][p][j] = v; break;
            default: g_WpD[l][p][j] = v; break;
        }
        return;
    }
    i -= 98304;
    if (i < 49152) {   // Wpost
        int j = i % 128, p = (i / 128) % 128, l = i / 16384;
        const float* src = Wpo + (size_t)l * 128 * 256;
        g_WpoT[l][p][j] = make_float2(src[(size_t)j * 256 + 2 * p],
                                      src[(size_t)j * 256 + 2 * p + 1]);
        return;
    }
    i -= 49152;
    if (i < 2944) {    // edge_W
        int j = i % 128, p = i / 128;
        float a = eW[(size_t)j * EAK + 2 * p];
        float b = (2 * p + 1 < EAK) ? eW[(size_t)j * EAK + 2 * p + 1] : 0.0f;
        g_eWT[p][j] = make_float2(a, b);
        return;
    }
    i -= 2944;
    if (i < 10 * IMG_ELEMS) {  // B images [k][n stride 136]
        int t = i / IMG_ELEMS, r = i % IMG_ELEMS, k = r / SB_STR, n = r % SB_STR;
        float v = 0.0f;
        if (n < 128) {
            if (t < 3)       v = We[(size_t)t * 49152 + (size_t)n * 384 + 256 + k];
            else if (t < 6)  v = Wp[(size_t)(t - 3) * 49152 + (size_t)n * 384 + 256 + k];
            else if (t == 6) v = W1[(size_t)n * 128 + k];
            else { int o = (t - 7) * 128 + n; if (o < OUTK) v = W2[(size_t)o * 128 + k]; }
        }
        ((uint32_t*)g_img)[i] = f2t(v);
        return;
    }
    i -= 10 * IMG_ELEMS;
    if (i < Ntot) g_deg[i] = 0.0f;
}

__global__ void k_count_deg(const int* __restrict__ ei, int Etot) {
    int i = blockIdx.x * blockDim.x + threadIdx.x;
    if (i < Etot) atomicAdd(&g_deg[ei[Etot + i]], 1.0f);
}

// ---------------------------------------------------------------------------
// fused init: blocks [0,N) node_init, blocks [N, N+ceil(E/16)) edge_init
__global__ void __launch_bounds__(128) k_init_fused(
        const float* __restrict__ pos, const int* __restrict__ pos_w,
        const float* __restrict__ wte, const float* __restrict__ nW,
        const float* __restrict__ nb,
        const float* __restrict__ ea, const int* __restrict__ et,
        const float* __restrict__ lemb, const float* __restrict__ eb,
        int Ntot, int Etot) {
    int j = threadIdx.x;
    if ((int)blockIdx.x < Ntot) {
        int n = blockIdx.x;
        __shared__ float s_pos[8];
        if (j < 8) s_pos[j] = pos[(size_t)n * 8 + j];
        __syncthreads();
        float acc = nb[j] + wte[(size_t)pos_w[n] * HIDN + j];
#pragma unroll
        for (int k = 0; k < 8; k++) acc += s_pos[k] * nW[j * 8 + k];
        g_x[(size_t)n * HIDN + j] = acc;
        return;
    }
    int e0 = (blockIdx.x - Ntot) * 16;
    __shared__ __align__(16) float s_a[16][46];
    __shared__ int s_t[16];
    int nv = min(16, Etot - e0);
    for (int idx = j; idx < nv * EAK; idx += 128) {
        int t = idx / EAK, k = idx % EAK;
        s_a[t][k] = ea[(size_t)(e0 + t) * EAK + k];
    }
    if (j < 16) { s_a[j][45] = 0.0f; s_t[j] = (j < nv) ? et[e0 + j] : 0; }
    __syncthreads();
    u64 acc[16];
#pragma unroll
    for (int t = 0; t < 16; t++) acc[t] = 0ull;
    const u64* wp = (const u64*)&g_eWT[0][0];
#pragma unroll
    for (int p = 0; p < 23; p++) {
        u64 w = wp[p * 128 + j];
#pragma unroll
        for (int t = 0; t < 16; t++)
            acc[t] = fma2(*(const u64*)&s_a[t][2 * p], w, acc[t]);
    }
    float ebj = eb[j];
    for (int t = 0; t < nv; t++)
        g_e[(size_t)(e0 + t) * HIDN + j] =
            lemb[(size_t)s_t[t] * HIDN + j] + hadd2(acc[t]) + ebj;
}

// ---------------------------------------------------------------------------
// node projections (scalar f32x2)
__global__ void __launch_bounds__(64) k_node_pre(int l, int Ntot) {
    int n0 = blockIdx.x * 16;
    int j0 = threadIdx.x;
    __shared__ __align__(16) float s_x[16][HIDN];
    int nv = min(16, Ntot - n0);
    for (int t = 0; t < 16; t++) {
        float a = 0.0f, b = 0.0f;
        if (t < nv) {
            a = g_x[(size_t)(n0 + t) * HIDN + j0];
            b = g_x[(size_t)(n0 + t) * HIDN + j0 + 64];
        }
        s_x[t][j0] = a; s_x[t][j0 + 64] = b;
    }
    __syncthreads();
    const u64* WT[4] = { (const u64*)&g_WeS[l][0][0], (const u64*)&g_WeD[l][0][0],
                         (const u64*)&g_WpS[l][0][0], (const u64*)&g_WpD[l][0][0] };
#pragma unroll
    for (int w = 0; w < 4; w++) {
        u64 acc0[16], acc1[16];
#pragma unroll
        for (int t = 0; t < 16; t++) { acc0[t] = 0ull; acc1[t] = 0ull; }
        const u64* wp = WT[w];
#pragma unroll 2
        for (int k4 = 0; k4 < 32; k4++) {
            u64 wA0 = wp[(2 * k4) * 128 + j0];
            u64 wA1 = wp[(2 * k4 + 1) * 128 + j0];
            u64 wB0 = wp[(2 * k4) * 128 + j0 + 64];
            u64 wB1 = wp[(2 * k4 + 1) * 128 + j0 + 64];
#pragma unroll
            for (int t = 0; t < 16; t++) {
                ulonglong2 xv = *(const ulonglong2*)&s_x[t][k4 * 4];
                acc0[t] = fma2(xv.x, wA0, acc0[t]);
                acc0[t] = fma2(xv.y, wA1, acc0[t]);
                acc1[t] = fma2(xv.x, wB0, acc1[t]);
                acc1[t] = fma2(xv.y, wB1, acc1[t]);
            }
        }
        for (int t = 0; t < nv; t++) {
            g_np[(size_t)(n0 + t) * 512 + w * HIDN + j0]      = hadd2(acc0[t]);
            g_np[(size_t)(n0 + t) * 512 + w * HIDN + j0 + 64] = hadd2(acc1[t]);
        }
    }
}

// ---------------------------------------------------------------------------
// TENSOR edge layer (mma.sync tf32): 128 edges/CTA, 256 threads
// smem floats: A 16896 | B 17408 | b1 128 | b2 128 | src 128 | dst 128
#define EL_A    0
#define EL_B    16896
#define EL_B1   34304
#define EL_B2   34432
#define EL_SRC  34560
#define EL_DST  34688
#define EL_SMEM (34816 * 4)

__global__ void __launch_bounds__(256) k_edge_layer_m(
        const int* __restrict__ ei, const float* __restrict__ be,
        const float* __restrict__ bpre, int l, int Etot) {
    extern __shared__ float sm[];
    uint32_t* sA = (uint32_t*)(sm + EL_A);
    uint32_t* sB = (uint32_t*)(sm + EL_B);
    float* sb1 = sm + EL_B1;
    float* sb2 = sm + EL_B2;
    int* ssrc = (int*)(sm + EL_SRC);
    int* sdst = (int*)(sm + EL_DST);

    int tid = threadIdx.x, lane = tid & 31, w = tid >> 5;
    int RO = (w >> 1) * 32, CO = (w & 1) * 64;
    int e0 = blockIdx.x * 128;
    int nv = min(128, Etot - e0);

    if (tid < 128) {
        sb1[tid] = be[tid];
        sb2[tid] = bpre[tid];
        int valid = tid < nv;
        ssrc[tid] = valid ? ei[e0 + tid] : 0;
        sdst[tid] = valid ? ei[Etot + e0 + tid] : 0;
    }
    // A <- e (tf32); B <- WeE image
    {
        const float4* src = (const float4*)(g_e + (size_t)e0 * HIDN);
        for (int i = tid; i < 4096; i += 256) {
            int r = i >> 5, k = (i & 31) << 2;
            uint4 t4 = make_uint4(0u, 0u, 0u, 0u);
            if (r < nv) {
                float4 v = src[i];
                t4 = make_uint4(f2t(v.x), f2t(v.y), f2t(v.z), f2t(v.w));
            }
            *(uint4*)&sA[r * SA_STR + k] = t4;
        }
        const uint4* ws = (const uint4*)&g_img[l][0];
        uint4* wd = (uint4*)sB;
        for (int i = tid; i < IMG_ELEMS / 4; i += 256) wd[i] = ws[i];
    }
    __syncthreads();

    float acc[2][8][4];
    zero_acc(acc);
    gemm_warp(sA, sB, RO, CO, lane, acc);
    __syncthreads();   // all sA/sB reads done

    int lr = lane >> 2, lc2 = (lane & 3) * 2;

    // epilogue 1: e' = silu(D + be + np_a1[src] + np_a2[dst]) -> g_e + sA(tf32)
#pragma unroll
    for (int rt = 0; rt < 2; rt++) {
        int r0 = RO + 16 * rt + lr, r1 = r0 + 8;
        const float* s0 = g_np + (size_t)ssrc[r0] * 512;
        const float* d0 = g_np + (size_t)sdst[r0] * 512 + 128;
        const float* s1 = g_np + (size_t)ssrc[r1] * 512;
        const float* d1 = g_np + (size_t)sdst[r1] * 512 + 128;
        float* ge0 = g_e + (size_t)(e0 + r0) * HIDN;
        float* ge1 = g_e + (size_t)(e0 + r1) * HIDN;
#pragma unroll
        for (int ct = 0; ct < 8; ct++) {
            int c = CO + 8 * ct + lc2;
            float2 ps0 = *(const float2*)(s0 + c), pd0 = *(const float2*)(d0 + c);
            float2 ps1 = *(const float2*)(s1 + c), pd1 = *(const float2*)(d1 + c);
            float b0v = sb1[c], b1v = sb1[c + 1];
            float v00 = siluf(acc[rt][ct][0] + b0v + ps0.x + pd0.x);
            float v01 = siluf(acc[rt][ct][1] + b1v + ps0.y + pd0.y);
            float v10 = siluf(acc[rt][ct][2] + b0v + ps1.x + pd1.x);
            float v11 = siluf(acc[rt][ct][3] + b1v + ps1.y + pd1.y);
            if (r0 < nv) *(float2*)(ge0 + c) = make_float2(v00, v01);
            if (r1 < nv) *(float2*)(ge1 + c) = make_float2(v10, v11);
            *(uint2*)&sA[r0 * SA_STR + c] = make_uint2(f2t(v00), f2t(v01));
            *(uint2*)&sA[r1 * SA_STR + c] = make_uint2(f2t(v10), f2t(v11));
        }
    }
    // B <- WpE image
    {
        const uint4* ws = (const uint4*)&g_img[3 + l][0];
        uint4* wd = (uint4*)sB;
        for (int i = tid; i < IMG_ELEMS / 4; i += 256) wd[i] = ws[i];
    }
    __syncthreads();

    zero_acc(acc);
    gemm_warp(sA, sB, RO, CO, lane, acc);

    // epilogue 2: m = silu(D + bpre + np_p1[src] + np_p2[dst]); agg[dst] += m
#pragma unroll
    for (int rt = 0; rt < 2; rt++) {
        int r0 = RO + 16 * rt + lr, r1 = r0 + 8;
        const float* s0 = g_np + (size_t)ssrc[r0] * 512 + 256;
        const float* d0 = g_np + (size_t)sdst[r0] * 512 + 384;
        const float* s1 = g_np + (size_t)ssrc[r1] * 512 + 256;
        const float* d1 = g_np + (size_t)sdst[r1] * 512 + 384;
        float* a0 = g_agg + (size_t)sdst[r0] * HIDN;
        float* a1 = g_agg + (size_t)sdst[r1] * HIDN;
#pragma unroll
        for (int ct = 0; ct < 8; ct++) {
            int c = CO + 8 * ct + lc2;
            float2 ps0 = *(const float2*)(s0 + c), pd0 = *(const float2*)(d0 + c);
            float2 ps1 = *(const float2*)(s1 + c), pd1 = *(const float2*)(d1 + c);
            float b0v = sb2[c], b1v = sb2[c + 1];
            float m00 = siluf(acc[rt][ct][0] + b0v + ps0.x + pd0.x);
            float m01 = siluf(acc[rt][ct][1] + b1v + ps0.y + pd0.y);
            float m10 = siluf(acc[rt][ct][2] + b0v + ps1.x + pd1.x);
            float m11 = siluf(acc[rt][ct][3] + b1v + ps1.y + pd1.y);
            if (r0 < nv) { atomicAdd(a0 + c, m00); atomicAdd(a0 + c + 1, m01); }
            if (r1 < nv) { atomicAdd(a1 + c, m10); atomicAdd(a1 + c + 1, m11); }
        }
    }
}

// ---------------------------------------------------------------------------
// x' = cat([x, agg/deg]) @ Wpost^T + bpost; re-zeroes g_agg
__global__ void __launch_bounds__(64) k_node_post(
        const float* __restrict__ bpost, int l, int do_silu, int Ntot) {
    int n0 = blockIdx.x * 16;
    int j0 = threadIdx.x;
    __shared__ __align__(16) float s_in[16][256];
    int nv = min(16, Ntot - n0);
    for (int t = 0; t < 16; t++) {
        float a = 0.f, b = 0.f, c = 0.f, d = 0.f;
        if (t < nv) {
            float inv = 1.0f / fmaxf(g_deg[n0 + t], 1.0f);
            size_t base = (size_t)(n0 + t) * HIDN;
            a = g_x[base + j0];
            b = g_x[base + j0 + 64];
            c = g_agg[base + j0] * inv;
            d = g_agg[base + j0 + 64] * inv;
            g_agg[base + j0] = 0.0f;
            g_agg[base + j0 + 64] = 0.0f;
        }
        s_in[t][j0] = a; s_in[t][j0 + 64] = b;
        s_in[t][128 + j0] = c; s_in[t][192 + j0] = d;
    }
    __syncthreads();
    u64 acc0[16], acc1[16];
#pragma unroll
    for (int t = 0; t < 16; t++) { acc0[t] = 0ull; acc1[t] = 0ull; }
    const u64* wp = (const u64*)&g_WpoT[l][0][0];
#pragma unroll 2
    for (int k4 = 0; k4 < 64; k4++) {
        u64 wA0 = wp[(2 * k4) * 128 + j0];
        u64 wA1 = wp[(2 * k4 + 1) * 128 + j0];
        u64 wB0 = wp[(2 * k4) * 128 + j0 + 64];
        u64 wB1 = wp[(2 * k4 + 1) * 128 + j0 + 64];
#pragma unroll
        for (int t = 0; t < 16; t++) {
            ulonglong2 iv = *(const ulonglong2*)&s_in[t][k4 * 4];
            acc0[t] = fma2(iv.x, wA0, acc0[t]);
            acc0[t] = fma2(iv.y, wA1, acc0[t]);
            acc1[t] = fma2(iv.x, wB0, acc1[t]);
            acc1[t] = fma2(iv.y, wB1, acc1[t]);
        }
    }
    float b0 = bpost[j0], b1 = bpost[j0 + 64];
    for (int t = 0; t < nv; t++) {
        float v0 = hadd2(acc0[t]) + b0;
        float v1 = hadd2(acc1[t]) + b1;
        size_t base = (size_t)(n0 + t) * HIDN;
        g_x[base + j0]      = do_silu ? siluf(v0) : v0;
        g_x[base + j0 + 64] = do_silu ? siluf(v1) : v1;
    }
}

__global__ void k_copy_x(float* __restrict__ out, int Ntot) {
    int i = blockIdx.x * blockDim.x + threadIdx.x;
    if (i < Ntot * HIDN) out[i] = g_x[i];
}

// ---------------------------------------------------------------------------
// TENSOR readout (mma.sync tf32): 128 edges/CTA, 256 threads
// smem floats: A 16896 | B 17408 | b1 128 | b2 384 | res 1536
#define RO_A    0
#define RO_B    16896
#define RO_B1   34304
#define RO_B2   34432
#define RO_RES  34816
#define RO_SMEM ((34816 + 1536) * 4)

__global__ void __launch_bounds__(256) k_readout_m(
        const float* __restrict__ ea, const float* __restrict__ b1,
        const float* __restrict__ b2, float* __restrict__ out, int Etot) {
    extern __shared__ float sm[];
    uint32_t* sA = (uint32_t*)(sm + RO_A);
    uint32_t* sB = (uint32_t*)(sm + RO_B);
    float* sb1 = sm + RO_B1;
    float* sb2 = sm + RO_B2;
    float* sres = sm + RO_RES;          // [128 rows][12] (9 used)

    int tid = threadIdx.x, lane = tid & 31, w = tid >> 5;
    int RO = (w >> 1) * 32, CO = (w & 1) * 64;
    int e0 = blockIdx.x * 128;
    int nv = min(128, Etot - e0);

    if (tid < 128) sb1[tid] = b1[tid];
    for (int i = tid; i < 384; i += 256) sb2[i] = (i < OUTK) ? b2[i] : 0.0f;
    for (int i = tid; i < 128 * 9; i += 256) {
        int r = i / 9, m = i % 9;
        sres[r * 12 + m] = (r < nv) ? ea[(size_t)(e0 + r) * EAK + m * 5 + 4] : 0.0f;
    }
    // A <- e; B <- W1 image
    {
        const float4* src = (const float4*)(g_e + (size_t)e0 * HIDN);
        for (int i = tid; i < 4096; i += 256) {
            int r = i >> 5, k = (i & 31) << 2;
            uint4 t4 = make_uint4(0u, 0u, 0u, 0u);
            if (r < nv) {
                float4 v = src[i];
                t4 = make_uint4(f2t(v.x), f2t(v.y), f2t(v.z), f2t(v.w));
            }
            *(uint4*)&sA[r * SA_STR + k] = t4;
        }
        const uint4* ws = (const uint4*)&g_img[6][0];
        uint4* wd = (uint4*)sB;
        for (int i = tid; i < IMG_ELEMS / 4; i += 256) wd[i] = ws[i];
    }
    __syncthreads();

    float acc[2][8][4];
    zero_acc(acc);
    gemm_warp(sA, sB, RO, CO, lane, acc);
    __syncthreads();

    int lr = lane >> 2, lc2 = (lane & 3) * 2;
    // h = silu(D + b1) -> sA (tf32)
#pragma unroll
    for (int rt = 0; rt < 2; rt++) {
        int r0 = RO + 16 * rt + lr, r1 = r0 + 8;
#pragma unroll
        for (int ct = 0; ct < 8; ct++) {
            int c = CO + 8 * ct + lc2;
            float b0v = sb1[c], b1v = sb1[c + 1];
            *(uint2*)&sA[r0 * SA_STR + c] =
                make_uint2(f2t(siluf(acc[rt][ct][0] + b0v)),
                           f2t(siluf(acc[rt][ct][1] + b1v)));
            *(uint2*)&sA[r1 * SA_STR + c] =
                make_uint2(f2t(siluf(acc[rt][ct][2] + b0v)),
                           f2t(siluf(acc[rt][ct][3] + b1v)));
        }
    }
    __syncthreads();

#pragma unroll 1
    for (int cc = 0; cc < 3; cc++) {
        // B <- W2 chunk cc
        const uint4* ws = (const uint4*)&g_img[7 + cc][0];
        uint4* wd = (uint4*)sB;
        for (int i = tid; i < IMG_ELEMS / 4; i += 256) wd[i] = ws[i];
        __syncthreads();
        zero_acc(acc);
        gemm_warp(sA, sB, RO, CO, lane, acc);
#pragma unroll
        for (int rt = 0; rt < 2; rt++) {
            int r0 = RO + 16 * rt + lr, r1 = r0 + 8;
            float* o0 = out + (size_t)(e0 + r0) * OUTK;
            float* o1 = out + (size_t)(e0 + r1) * OUTK;
#pragma unroll
            for (int ct = 0; ct < 8; ct++) {
                int o = cc * 128 + CO + 8 * ct + lc2;
                if (o < OUTK) {
                    int mf = o / 40;   // pair never straddles a 40-boundary
                    float bb0 = sb2[o], bb1 = sb2[o + 1];
                    if (r0 < nv) {
                        float rr = sres[r0 * 12 + mf];
                        *(float2*)(o0 + o) = make_float2(acc[rt][ct][0] + bb0 + rr,
                                                         acc[rt][ct][1] + bb1 + rr);
                    }
                    if (r1 < nv) {
                        float rr = sres[r1 * 12 + mf];
                        *(float2*)(o1 + o) = make_float2(acc[rt][ct][2] + bb0 + rr,
                                                         acc[rt][ct][3] + bb1 + rr);
                    }
                }
            }
        }
        __syncthreads();   // sB reads done before next copy
    }
}

// ===========================================================================
extern "C" void kernel_launch(void* const* d_in, const int* in_sizes, int n_in,
                              void* d_out, int out_size) {
    const float* edge_attr   = (const float*)d_in[0];
    const int*   edge_type   = (const int*)  d_in[1];
    const float* pos         = (const float*)d_in[2];
    const int*   pos_w       = (const int*)  d_in[3];
    const int*   edge_index  = (const int*)  d_in[4];
    const float* layer_embed = (const float*)d_in[5];
    const float* wte         = (const float*)d_in[6];
    const float* node_W      = (const float*)d_in[7];
    const float* node_b      = (const float*)d_in[8];
    const float* edge_W      = (const float*)d_in[9];
    const float* edge_b      = (const float*)d_in[10];
    const float* gnn_We      = (const float*)d_in[11];
    const float* gnn_be      = (const float*)d_in[12];
    const float* gnn_Wpre    = (const float*)d_in[13];
    const float* gnn_bpre    = (const float*)d_in[14];
    const float* gnn_Wpost   = (const float*)d_in[15];
    const float* gnn_bpost   = (const float*)d_in[16];
    const float* out_W1      = (const float*)d_in[17];
    const float* out_b1      = (const float*)d_in[18];
    const float* out_W2      = (const float*)d_in[19];
    const float* out_b2      = (const float*)d_in[20];

    int E = in_sizes[1];
    int N = in_sizes[3];
    if (E > EE) E = EE;
    if (N > NN) N = NN;

    float* outp = (float*)d_out;
    float* out_x = nullptr; float* out_o = nullptr;
    long xsz = (long)N * HIDN, osz = (long)E * OUTK;
    if ((long)out_size >= xsz + osz)      { out_x = outp; out_o = outp + xsz; }
    else if ((long)out_size == osz)       { out_o = outp; }
    else                                  { out_x = outp; }

    cudaFuncSetAttribute(k_edge_layer_m, cudaFuncAttributeMaxDynamicSharedMemorySize, EL_SMEM);
    cudaFuncSetAttribute(k_readout_m,    cudaFuncAttributeMaxDynamicSharedMemorySize, RO_SMEM);

    int EB16 = (E + 15) / 16, NB = (N + 15) / 16, EB128 = (E + 127) / 128;
    int packN = 98304 + 49152 + 2944 + 10 * IMG_ELEMS + N;

    k_pack_all<<<(packN + 255) / 256, 256>>>(gnn_We, gnn_Wpre, gnn_Wpost,
                                             out_W1, out_W2, edge_W, N);          // 1
    k_init_fused<<<N + EB16, 128>>>(pos, pos_w, wte, node_W, node_b,
                                    edge_attr, edge_type, layer_embed, edge_b,
                                    N, E);                                        // 2
    k_node_pre<<<NB, 64>>>(0, N);                                                 // 3
    k_edge_layer_m<<<EB128, 256, EL_SMEM>>>(edge_index, gnn_be, gnn_bpre, 0, E);  // 4 (profiled)
    k_count_deg<<<(E + 255) / 256, 256>>>(edge_index, E);                         // 5
    k_node_post<<<NB, 64>>>(gnn_bpost, 0, 1, N);                                  // 6

    for (int l = 1; l < NL; l++) {
        k_node_pre<<<NB, 64>>>(l, N);
        k_edge_layer_m<<<EB128, 256, EL_SMEM>>>(edge_index,
                                                gnn_be + l * HIDN,
                                                gnn_bpre + l * HIDN, l, E);
        k_node_post<<<NB, 64>>>(gnn_bpost + l * HIDN, l, (l < NL - 1) ? 1 : 0, N);
    }

    if (out_x) k_copy_x<<<((long)N * HIDN + 255) / 256, 256>>>(out_x, N);
    if (out_o) k_readout_m<<<EB128, 256, RO_SMEM>>>(edge_attr, out_b1, out_b2, out_o, E);
}

// round 7
// speedup vs baseline: 2.4636x; 1.3778x over previous
#include <cuda_runtime.h>
#include <math.h>
#include <stdint.h>

#define NN   50000
#define EE   400000
#define HIDN 128
#define EAK  45
#define OUTK 360
#define NL   3

typedef unsigned long long u64;

// ---- scratch ----
__device__ __align__(16) float g_x   [(size_t)NN * HIDN];
__device__ __align__(16) float g_e   [(size_t)EE * HIDN];
__device__ __align__(16) float g_np  [(size_t)NN * 4 * HIDN];
__device__ __align__(16) float g_agg [(size_t)NN * HIDN];   // kept zero between layers
__device__              float g_deg  [NN];

__device__ __align__(16) float2 g_eWT[23][128];   // edge_W scalar pack (init only)

// tf32 B images: [k(128)][n stride 136].
// 0..2 WeE[l] | 3..5 WpE[l] | 6 W1 | 7..9 W2 chunks | 10..12 WeS[l] | 13..15 WeD[l]
// 16..18 WpS[l] | 19..21 WpD[l] | 22..27 Wpost[l] k-chunks (22+2l+c)
#define IMG_ELEMS 17408     // 128*136
#define N_IMG 28
__device__ __align__(16) uint32_t g_img[N_IMG][IMG_ELEMS];

__device__ __forceinline__ float siluf(float v) {
    return v * (1.0f / (1.0f + __expf(-v)));
}
__device__ __forceinline__ u64 fma2(u64 a, u64 b, u64 c) {
    u64 d;
    asm("fma.rn.f32x2 %0, %1, %2, %3;" : "=l"(d) : "l"(a), "l"(b), "l"(c));
    return d;
}
__device__ __forceinline__ float hadd2(u64 v) {
    float lo, hi;
    asm("mov.b64 {%0, %1}, %2;" : "=f"(lo), "=f"(hi) : "l"(v));
    return lo + hi;
}
__device__ __forceinline__ uint32_t f2t(float v) {
    uint32_t o;
    asm("cvt.rna.tf32.f32 %0, %1;" : "=r"(o) : "f"(v));
    return o;
}

// ===================== warp tf32 MMA: 16 rows x 64 cols, k=128 ============
__device__ __forceinline__ void mma1688(float d[4], const uint32_t a[4],
                                        uint32_t b0, uint32_t b1) {
    asm volatile(
        "mma.sync.aligned.m16n8k8.row.col.f32.tf32.tf32.f32 "
        "{%0,%1,%2,%3}, {%4,%5,%6,%7}, {%8,%9}, {%0,%1,%2,%3};\n"
        : "+f"(d[0]), "+f"(d[1]), "+f"(d[2]), "+f"(d[3])
        : "r"(a[0]), "r"(a[1]), "r"(a[2]), "r"(a[3]), "r"(b0), "r"(b1));
}
#define SB_STR 136

__device__ __forceinline__ void gemm16(const uint32_t* __restrict__ sA, int strA,
                                       int kbase, const uint32_t* __restrict__ sB,
                                       int RO, int CO, int lane, float acc[8][4]) {
    int lr = lane >> 2, lc = lane & 3;
#pragma unroll 4
    for (int k = 0; k < 128; k += 8) {
        uint32_t a[4];
        a[0] = sA[(RO + lr)     * strA + kbase + k + lc];
        a[1] = sA[(RO + lr + 8) * strA + kbase + k + lc];
        a[2] = sA[(RO + lr)     * strA + kbase + k + 4 + lc];
        a[3] = sA[(RO + lr + 8) * strA + kbase + k + 4 + lc];
#pragma unroll
        for (int ct = 0; ct < 8; ct++) {
            uint32_t b0 = sB[(k + lc)     * SB_STR + CO + 8 * ct + lr];
            uint32_t b1 = sB[(k + 4 + lc) * SB_STR + CO + 8 * ct + lr];
            mma1688(acc[ct], a, b0, b1);
        }
    }
}
__device__ __forceinline__ void zacc(float acc[8][4]) {
#pragma unroll
    for (int j = 0; j < 8; j++)
#pragma unroll
        for (int q = 0; q < 4; q++) acc[j][q] = 0.0f;
}

// ---------------------------------------------------------------------------
__global__ void k_pack_all(const float* __restrict__ We, const float* __restrict__ Wp,
                           const float* __restrict__ Wpo, const float* __restrict__ W1,
                           const float* __restrict__ W2, const float* __restrict__ eW,
                           int Ntot) {
    int i = blockIdx.x * blockDim.x + threadIdx.x;
    if (i < 2944) {
        int j = i % 128, p = i / 128;
        float a = eW[(size_t)j * EAK + 2 * p];
        float b = (2 * p + 1 < EAK) ? eW[(size_t)j * EAK + 2 * p + 1] : 0.0f;
        g_eWT[p][j] = make_float2(a, b);
        return;
    }
    i -= 2944;
    if (i < N_IMG * IMG_ELEMS) {
        int t = i / IMG_ELEMS, r = i % IMG_ELEMS, k = r / SB_STR, n = r % SB_STR;
        float v = 0.0f;
        if (n < 128) {
            if (t < 3)        v = We[(size_t)t * 49152 + (size_t)n * 384 + 256 + k];
            else if (t < 6)   v = Wp[(size_t)(t - 3) * 49152 + (size_t)n * 384 + 256 + k];
            else if (t == 6)  v = W1[(size_t)n * 128 + k];
            else if (t < 10)  { int o = (t - 7) * 128 + n; if (o < OUTK) v = W2[(size_t)o * 128 + k]; }
            else if (t < 13)  v = We[(size_t)(t - 10) * 49152 + (size_t)n * 384 + k];
            else if (t < 16)  v = We[(size_t)(t - 13) * 49152 + (size_t)n * 384 + 128 + k];
            else if (t < 19)  v = Wp[(size_t)(t - 16) * 49152 + (size_t)n * 384 + k];
            else if (t < 22)  v = Wp[(size_t)(t - 19) * 49152 + (size_t)n * 384 + 128 + k];
            else {
                int l = (t - 22) >> 1, c = (t - 22) & 1;
                v = Wpo[(size_t)l * 32768 + (size_t)n * 256 + 128 * c + k];
            }
        }
        ((uint32_t*)g_img)[i] = f2t(v);
        return;
    }
    i -= N_IMG * IMG_ELEMS;
    if (i < Ntot) g_deg[i] = 0.0f;
}

__global__ void k_count_deg(const int* __restrict__ ei, int Etot) {
    int i = blockIdx.x * blockDim.x + threadIdx.x;
    if (i < Etot) atomicAdd(&g_deg[ei[Etot + i]], 1.0f);
}

// ---------------------------------------------------------------------------
// fused init: blocks [0,N) node_init, blocks [N, N+ceil(E/16)) edge_init
__global__ void __launch_bounds__(128) k_init_fused(
        const float* __restrict__ pos, const int* __restrict__ pos_w,
        const float* __restrict__ wte, const float* __restrict__ nW,
        const float* __restrict__ nb,
        const float* __restrict__ ea, const int* __restrict__ et,
        const float* __restrict__ lemb, const float* __restrict__ eb,
        int Ntot, int Etot) {
    int j = threadIdx.x;
    if ((int)blockIdx.x < Ntot) {
        int n = blockIdx.x;
        __shared__ float s_pos[8];
        if (j < 8) s_pos[j] = pos[(size_t)n * 8 + j];
        __syncthreads();
        float acc = nb[j] + wte[(size_t)pos_w[n] * HIDN + j];
#pragma unroll
        for (int k = 0; k < 8; k++) acc += s_pos[k] * nW[j * 8 + k];
        g_x[(size_t)n * HIDN + j] = acc;
        return;
    }
    int e0 = (blockIdx.x - Ntot) * 16;
    __shared__ __align__(16) float s_a[16][46];
    __shared__ int s_t[16];
    int nv = min(16, Etot - e0);
    for (int idx = j; idx < nv * EAK; idx += 128) {
        int t = idx / EAK, k = idx % EAK;
        s_a[t][k] = ea[(size_t)(e0 + t) * EAK + k];
    }
    if (j < 16) { s_a[j][45] = 0.0f; s_t[j] = (j < nv) ? et[e0 + j] : 0; }
    __syncthreads();
    u64 acc[16];
#pragma unroll
    for (int t = 0; t < 16; t++) acc[t] = 0ull;
    const u64* wp = (const u64*)&g_eWT[0][0];
#pragma unroll
    for (int p = 0; p < 23; p++) {
        u64 w = wp[p * 128 + j];
#pragma unroll
        for (int t = 0; t < 16; t++)
            acc[t] = fma2(*(const u64*)&s_a[t][2 * p], w, acc[t]);
    }
    float ebj = eb[j];
    for (int t = 0; t < nv; t++)
        g_e[(size_t)(e0 + t) * HIDN + j] =
            lemb[(size_t)s_t[t] * HIDN + j] + hadd2(acc[t]) + ebj;
}

// ---------------------------------------------------------------------------
// TENSOR node_pre: 64 nodes/CTA, 4 GEMMs -> g_np
#define NP_STR  132
#define NP_SMEM ((64 * NP_STR + IMG_ELEMS) * 4)
__global__ void __launch_bounds__(256, 2) k_node_pre_m(int l, int Ntot) {
    extern __shared__ float sm[];
    uint32_t* sA = (uint32_t*)sm;
    uint32_t* sB = (uint32_t*)sm + 64 * NP_STR;
    int tid = threadIdx.x, lane = tid & 31, w = tid >> 5;
    int RO = (w >> 1) * 16, CO = (w & 1) * 64;
    int n0 = blockIdx.x * 64;
    int nv = min(64, Ntot - n0);

    const float4* src = (const float4*)(g_x + (size_t)n0 * HIDN);
    for (int i = tid; i < 2048; i += 256) {
        int r = i >> 5, k = (i & 31) << 2;
        uint4 t4 = make_uint4(0u, 0u, 0u, 0u);
        if (r < nv) {
            float4 v = src[i];
            t4 = make_uint4(f2t(v.x), f2t(v.y), f2t(v.z), f2t(v.w));
        }
        *(uint4*)&sA[r * NP_STR + k] = t4;
    }

    int lr = lane >> 2, lc2 = (lane & 3) * 2;
    const int imgs[4] = { 10 + l, 13 + l, 16 + l, 19 + l };
#pragma unroll 1
    for (int blk = 0; blk < 4; blk++) {
        const uint4* ws = (const uint4*)&g_img[imgs[blk]][0];
        uint4* wd = (uint4*)sB;
        for (int i = tid; i < IMG_ELEMS / 4; i += 256) wd[i] = ws[i];
        __syncthreads();
        float acc[8][4];
        zacc(acc);
        gemm16(sA, NP_STR, 0, sB, RO, CO, lane, acc);
        int r0 = RO + lr, r1 = r0 + 8;
#pragma unroll
        for (int ct = 0; ct < 8; ct++) {
            int c = blk * 128 + CO + 8 * ct + lc2;
            if (r0 < nv) *(float2*)&g_np[(size_t)(n0 + r0) * 512 + c] =
                make_float2(acc[ct][0], acc[ct][1]);
            if (r1 < nv) *(float2*)&g_np[(size_t)(n0 + r1) * 512 + c] =
                make_float2(acc[ct][2], acc[ct][3]);
        }
        __syncthreads();
    }
}

// ---------------------------------------------------------------------------
// TENSOR edge layer: 64 edges/CTA, 2 CTAs/SM
#define EL_A    0
#define EL_B    (64 * 132)               // 8448
#define EL_B1   (EL_B + IMG_ELEMS)       // 25856
#define EL_B2   (EL_B1 + 128)
#define EL_SRC  (EL_B2 + 128)
#define EL_DST  (EL_SRC + 64)
#define EL_SMEM ((EL_DST + 64) * 4)

__global__ void __launch_bounds__(256, 2) k_edge_layer_m(
        const int* __restrict__ ei, const float* __restrict__ be,
        const float* __restrict__ bpre, int l, int Etot) {
    extern __shared__ float sm[];
    uint32_t* sA = (uint32_t*)(sm + EL_A);
    uint32_t* sB = (uint32_t*)(sm + EL_B);
    float* sb1 = sm + EL_B1;
    float* sb2 = sm + EL_B2;
    int* ssrc = (int*)(sm + EL_SRC);
    int* sdst = (int*)(sm + EL_DST);

    int tid = threadIdx.x, lane = tid & 31, w = tid >> 5;
    int RO = (w >> 1) * 16, CO = (w & 1) * 64;
    int e0 = blockIdx.x * 64;
    int nv = min(64, Etot - e0);

    if (tid < 128) { sb1[tid] = be[tid]; sb2[tid] = bpre[tid]; }
    else if (tid < 192) {
        int t = tid - 128, valid = t < nv;
        ssrc[t] = valid ? ei[e0 + t] : 0;
        sdst[t] = valid ? ei[Etot + e0 + t] : 0;
    }
    {
        const float4* src = (const float4*)(g_e + (size_t)e0 * HIDN);
        for (int i = tid; i < 2048; i += 256) {
            int r = i >> 5, k = (i & 31) << 2;
            uint4 t4 = make_uint4(0u, 0u, 0u, 0u);
            if (r < nv) {
                float4 v = src[i];
                t4 = make_uint4(f2t(v.x), f2t(v.y), f2t(v.z), f2t(v.w));
            }
            *(uint4*)&sA[r * 132 + k] = t4;
        }
        const uint4* ws = (const uint4*)&g_img[l][0];
        uint4* wd = (uint4*)sB;
        for (int i = tid; i < IMG_ELEMS / 4; i += 256) wd[i] = ws[i];
    }
    __syncthreads();

    float acc[8][4];
    zacc(acc);
    gemm16(sA, 132, 0, sB, RO, CO, lane, acc);
    __syncthreads();

    int lr = lane >> 2, lc2 = (lane & 3) * 2;
    int r0 = RO + lr, r1 = r0 + 8;

    // epilogue 1: e' = silu(D + be + np_a1[src] + np_a2[dst]) -> g_e + sA
    {
        const float* s0 = g_np + (size_t)ssrc[r0] * 512;
        const float* d0 = g_np + (size_t)sdst[r0] * 512 + 128;
        const float* s1 = g_np + (size_t)ssrc[r1] * 512;
        const float* d1 = g_np + (size_t)sdst[r1] * 512 + 128;
        float* ge0 = g_e + (size_t)(e0 + r0) * HIDN;
        float* ge1 = g_e + (size_t)(e0 + r1) * HIDN;
#pragma unroll
        for (int ct = 0; ct < 8; ct++) {
            int c = CO + 8 * ct + lc2;
            float2 ps0 = *(const float2*)(s0 + c), pd0 = *(const float2*)(d0 + c);
            float2 ps1 = *(const float2*)(s1 + c), pd1 = *(const float2*)(d1 + c);
            float b0v = sb1[c], b1v = sb1[c + 1];
            float v00 = siluf(acc[ct][0] + b0v + ps0.x + pd0.x);
            float v01 = siluf(acc[ct][1] + b1v + ps0.y + pd0.y);
            float v10 = siluf(acc[ct][2] + b0v + ps1.x + pd1.x);
            float v11 = siluf(acc[ct][3] + b1v + ps1.y + pd1.y);
            if (r0 < nv) *(float2*)(ge0 + c) = make_float2(v00, v01);
            if (r1 < nv) *(float2*)(ge1 + c) = make_float2(v10, v11);
            *(uint2*)&sA[r0 * 132 + c] = make_uint2(f2t(v00), f2t(v01));
            *(uint2*)&sA[r1 * 132 + c] = make_uint2(f2t(v10), f2t(v11));
        }
    }
    {
        const uint4* ws = (const uint4*)&g_img[3 + l][0];
        uint4* wd = (uint4*)sB;
        for (int i = tid; i < IMG_ELEMS / 4; i += 256) wd[i] = ws[i];
    }
    __syncthreads();

    zacc(acc);
    gemm16(sA, 132, 0, sB, RO, CO, lane, acc);

    // epilogue 2: m = silu(D + bpre + np_p1[src] + np_p2[dst]); agg[dst] += m
    {
        const float* s0 = g_np + (size_t)ssrc[r0] * 512 + 256;
        const float* d0 = g_np + (size_t)sdst[r0] * 512 + 384;
        const float* s1 = g_np + (size_t)ssrc[r1] * 512 + 256;
        const float* d1 = g_np + (size_t)sdst[r1] * 512 + 384;
        float* a0 = g_agg + (size_t)sdst[r0] * HIDN;
        float* a1 = g_agg + (size_t)sdst[r1] * HIDN;
#pragma unroll
        for (int ct = 0; ct < 8; ct++) {
            int c = CO + 8 * ct + lc2;
            float2 ps0 = *(const float2*)(s0 + c), pd0 = *(const float2*)(d0 + c);
            float2 ps1 = *(const float2*)(s1 + c), pd1 = *(const float2*)(d1 + c);
            float b0v = sb2[c], b1v = sb2[c + 1];
            float m00 = siluf(acc[ct][0] + b0v + ps0.x + pd0.x);
            float m01 = siluf(acc[ct][1] + b1v + ps0.y + pd0.y);
            float m10 = siluf(acc[ct][2] + b0v + ps1.x + pd1.x);
            float m11 = siluf(acc[ct][3] + b1v + ps1.y + pd1.y);
            if (r0 < nv) { atomicAdd(a0 + c, m00); atomicAdd(a0 + c + 1, m01); }
            if (r1 < nv) { atomicAdd(a1 + c, m10); atomicAdd(a1 + c + 1, m11); }
        }
    }
}

// ---------------------------------------------------------------------------
// TENSOR node_post: 32 nodes/CTA, 128 threads; K=256 via 2 accumulating chunks
#define PO_STR  264
#define PO_B    (32 * PO_STR)            // 8448
#define PO_BIA  (PO_B + IMG_ELEMS)       // 25856
#define PO_INV  (PO_BIA + 128)
#define PO_SMEM ((PO_INV + 32) * 4)
__global__ void __launch_bounds__(128, 2) k_node_post_m(
        const float* __restrict__ bpost, int l, int do_silu, int Ntot) {
    extern __shared__ float sm[];
    uint32_t* sA = (uint32_t*)sm;
    uint32_t* sB = (uint32_t*)sm + PO_B;
    float* sbias = sm + PO_BIA;
    float* sinv  = sm + PO_INV;

    int tid = threadIdx.x, lane = tid & 31, w = tid >> 5;
    int RO = (w >> 1) * 16, CO = (w & 1) * 64;
    int n0 = blockIdx.x * 32;
    int nv = min(32, Ntot - n0);

    if (tid < 128) sbias[tid] = bpost[tid];
    if (tid < 32) sinv[tid] = (tid < nv) ? 1.0f / fmaxf(g_deg[n0 + tid], 1.0f) : 0.0f;
    __syncthreads();

    for (int i = tid; i < 2048; i += 128) {
        int r = i >> 6, k = (i & 63) << 2;
        uint4 t4 = make_uint4(0u, 0u, 0u, 0u);
        if (r < nv) {
            if (k < 128) {
                float4 v = *(const float4*)(g_x + (size_t)(n0 + r) * HIDN + k);
                t4 = make_uint4(f2t(v.x), f2t(v.y), f2t(v.z), f2t(v.w));
            } else {
                float inv = sinv[r];
                float* ap = g_agg + (size_t)(n0 + r) * HIDN + (k - 128);
                float4 v = *(const float4*)ap;
                t4 = make_uint4(f2t(v.x * inv), f2t(v.y * inv), f2t(v.z * inv), f2t(v.w * inv));
                *(float4*)ap = make_float4(0.f, 0.f, 0.f, 0.f);  // re-zero for next layer
            }
        }
        *(uint4*)&sA[r * PO_STR + k] = t4;
    }

    float acc[8][4];
    zacc(acc);
#pragma unroll 1
    for (int cchunk = 0; cchunk < 2; cchunk++) {
        const uint4* ws = (const uint4*)&g_img[22 + 2 * l + cchunk][0];
        uint4* wd = (uint4*)sB;
        for (int i = tid; i < IMG_ELEMS / 4; i += 128) wd[i] = ws[i];
        __syncthreads();
        gemm16(sA, PO_STR, cchunk * 128, sB, RO, CO, lane, acc);
        __syncthreads();
    }

    int lr = lane >> 2, lc2 = (lane & 3) * 2;
    int r0 = RO + lr, r1 = r0 + 8;
#pragma unroll
    for (int ct = 0; ct < 8; ct++) {
        int c = CO + 8 * ct + lc2;
        float b0v = sbias[c], b1v = sbias[c + 1];
        float v00 = acc[ct][0] + b0v, v01 = acc[ct][1] + b1v;
        float v10 = acc[ct][2] + b0v, v11 = acc[ct][3] + b1v;
        if (do_silu) { v00 = siluf(v00); v01 = siluf(v01); v10 = siluf(v10); v11 = siluf(v11); }
        if (r0 < nv) *(float2*)&g_x[(size_t)(n0 + r0) * HIDN + c] = make_float2(v00, v01);
        if (r1 < nv) *(float2*)&g_x[(size_t)(n0 + r1) * HIDN + c] = make_float2(v10, v11);
    }
}

__global__ void k_copy_x(float* __restrict__ out, int Ntot) {
    int i = blockIdx.x * blockDim.x + threadIdx.x;
    if (i < Ntot * HIDN) out[i] = g_x[i];
}

// ---------------------------------------------------------------------------
// TENSOR readout: 64 edges/CTA
#define RD_A    0
#define RD_B    (64 * 132)
#define RD_B1   (RD_B + IMG_ELEMS)       // 25856
#define RD_B2   (RD_B1 + 128)
#define RD_RES  (RD_B2 + 384)
#define RD_SMEM ((RD_RES + 64 * 12) * 4)

__global__ void __launch_bounds__(256, 2) k_readout_m(
        const float* __restrict__ ea, const float* __restrict__ b1,
        const float* __restrict__ b2, float* __restrict__ out, int Etot) {
    extern __shared__ float sm[];
    uint32_t* sA = (uint32_t*)(sm + RD_A);
    uint32_t* sB = (uint32_t*)(sm + RD_B);
    float* sb1 = sm + RD_B1;
    float* sb2 = sm + RD_B2;
    float* sres = sm + RD_RES;      // [64 rows][12] (9 used)

    int tid = threadIdx.x, lane = tid & 31, w = tid >> 5;
    int RO = (w >> 1) * 16, CO = (w & 1) * 64;
    int e0 = blockIdx.x * 64;
    int nv = min(64, Etot - e0);

    if (tid < 128) sb1[tid] = b1[tid];
    for (int i = tid; i < 384; i += 256) sb2[i] = (i < OUTK) ? b2[i] : 0.0f;
    for (int i = tid; i < 64 * 9; i += 256) {
        int r = i / 9, m = i % 9;
        sres[r * 12 + m] = (r < nv) ? ea[(size_t)(e0 + r) * EAK + m * 5 + 4] : 0.0f;
    }
    {
        const float4* src = (const float4*)(g_e + (size_t)e0 * HIDN);
        for (int i = tid; i < 2048; i += 256) {
            int r = i >> 5, k = (i & 31) << 2;
            uint4 t4 = make_uint4(0u, 0u, 0u, 0u);
            if (r < nv) {
                float4 v = src[i];
                t4 = make_uint4(f2t(v.x), f2t(v.y), f2t(v.z), f2t(v.w));
            }
            *(uint4*)&sA[r * 132 + k] = t4;
        }
        const uint4* ws = (const uint4*)&g_img[6][0];
        uint4* wd = (uint4*)sB;
        for (int i = tid; i < IMG_ELEMS / 4; i += 256) wd[i] = ws[i];
    }
    __syncthreads();

    float acc[8][4];
    zacc(acc);
    gemm16(sA, 132, 0, sB, RO, CO, lane, acc);
    __syncthreads();

    int lr = lane >> 2, lc2 = (lane & 3) * 2;
    int r0 = RO + lr, r1 = r0 + 8;
#pragma unroll
    for (int ct = 0; ct < 8; ct++) {
        int c = CO + 8 * ct + lc2;
        float b0v = sb1[c], b1v = sb1[c + 1];
        *(uint2*)&sA[r0 * 132 + c] = make_uint2(f2t(siluf(acc[ct][0] + b0v)),
                                                f2t(siluf(acc[ct][1] + b1v)));
        *(uint2*)&sA[r1 * 132 + c] = make_uint2(f2t(siluf(acc[ct][2] + b0v)),
                                                f2t(siluf(acc[ct][3] + b1v)));
    }
    __syncthreads();

#pragma unroll 1
    for (int cc = 0; cc < 3; cc++) {
        const uint4* ws = (const uint4*)&g_img[7 + cc][0];
        uint4* wd = (uint4*)sB;
        for (int i = tid; i < IMG_ELEMS / 4; i += 256) wd[i] = ws[i];
        __syncthreads();
        zacc(acc);
        gemm16(sA, 132, 0, sB, RO, CO, lane, acc);
        float* o0 = out + (size_t)(e0 + r0) * OUTK;
        float* o1 = out + (size_t)(e0 + r1) * OUTK;
#pragma unroll
        for (int ct = 0; ct < 8; ct++) {
            int o = cc * 128 + CO + 8 * ct + lc2;
            if (o < OUTK) {
                int mf = o / 40;
                float bb0 = sb2[o], bb1 = sb2[o + 1];
                if (r0 < nv) {
                    float rr = sres[r0 * 12 + mf];
                    *(float2*)(o0 + o) = make_float2(acc[ct][0] + bb0 + rr,
                                                     acc[ct][1] + bb1 + rr);
                }
                if (r1 < nv) {
                    float rr = sres[r1 * 12 + mf];
                    *(float2*)(o1 + o) = make_float2(acc[ct][2] + bb0 + rr,
                                                     acc[ct][3] + bb1 + rr);
                }
            }
        }
        __syncthreads();
    }
}

// ===========================================================================
extern "C" void kernel_launch(void* const* d_in, const int* in_sizes, int n_in,
                              void* d_out, int out_size) {
    const float* edge_attr   = (const float*)d_in[0];
    const int*   edge_type   = (const int*)  d_in[1];
    const float* pos         = (const float*)d_in[2];
    const int*   pos_w       = (const int*)  d_in[3];
    const int*   edge_index  = (const int*)  d_in[4];
    const float* layer_embed = (const float*)d_in[5];
    const float* wte         = (const float*)d_in[6];
    const float* node_W      = (const float*)d_in[7];
    const float* node_b      = (const float*)d_in[8];
    const float* edge_W      = (const float*)d_in[9];
    const float* edge_b      = (const float*)d_in[10];
    const float* gnn_We      = (const float*)d_in[11];
    const float* gnn_be      = (const float*)d_in[12];
    const float* gnn_Wpre    = (const float*)d_in[13];
    const float* gnn_bpre    = (const float*)d_in[14];
    const float* gnn_Wpost   = (const float*)d_in[15];
    const float* gnn_bpost   = (const float*)d_in[16];
    const float* out_W1      = (const float*)d_in[17];
    const float* out_b1      = (const float*)d_in[18];
    const float* out_W2      = (const float*)d_in[19];
    const float* out_b2      = (const float*)d_in[20];

    int E = in_sizes[1];
    int N = in_sizes[3];
    if (E > EE) E = EE;
    if (N > NN) N = NN;

    float* outp = (float*)d_out;
    float* out_x = nullptr; float* out_o = nullptr;
    long xsz = (long)N * HIDN, osz = (long)E * OUTK;
    if ((long)out_size >= xsz + osz)      { out_x = outp; out_o = outp + xsz; }
    else if ((long)out_size == osz)       { out_o = outp; }
    else                                  { out_x = outp; }

    cudaFuncSetAttribute(k_edge_layer_m, cudaFuncAttributeMaxDynamicSharedMemorySize, EL_SMEM);
    cudaFuncSetAttribute(k_readout_m,    cudaFuncAttributeMaxDynamicSharedMemorySize, RD_SMEM);
    cudaFuncSetAttribute(k_node_pre_m,   cudaFuncAttributeMaxDynamicSharedMemorySize, NP_SMEM);
    cudaFuncSetAttribute(k_node_post_m,  cudaFuncAttributeMaxDynamicSharedMemorySize, PO_SMEM);

    int EB16 = (E + 15) / 16;
    int EB64 = (E + 63) / 64, NB64 = (N + 63) / 64, NB32 = (N + 31) / 32;
    int packN = 2944 + N_IMG * IMG_ELEMS + N;

    k_pack_all<<<(packN + 255) / 256, 256>>>(gnn_We, gnn_Wpre, gnn_Wpost,
                                             out_W1, out_W2, edge_W, N);          // 1
    k_init_fused<<<N + EB16, 128>>>(pos, pos_w, wte, node_W, node_b,
                                    edge_attr, edge_type, layer_embed, edge_b,
                                    N, E);                                        // 2
    k_node_pre_m<<<NB64, 256, NP_SMEM>>>(0, N);                                   // 3
    k_edge_layer_m<<<EB64, 256, EL_SMEM>>>(edge_index, gnn_be, gnn_bpre, 0, E);   // 4 (profiled)
    k_count_deg<<<(E + 255) / 256, 256>>>(edge_index, E);                         // 5
    k_node_post_m<<<NB32, 128, PO_SMEM>>>(gnn_bpost, 0, 1, N);                    // 6

    for (int l = 1; l < NL; l++) {
        k_node_pre_m<<<NB64, 256, NP_SMEM>>>(l, N);
        k_edge_layer_m<<<EB64, 256, EL_SMEM>>>(edge_index,
                                               gnn_be + l * HIDN,
                                               gnn_bpre + l * HIDN, l, E);
        k_node_post_m<<<NB32, 128, PO_SMEM>>>(gnn_bpost + l * HIDN, l,
                                              (l < NL - 1) ? 1 : 0, N);
    }

    if (out_x) k_copy_x<<<((long)N * HIDN + 255) / 256, 256>>>(out_x, N);
    if (out_o) k_readout_m<<<EB64, 256, RD_SMEM>>>(edge_attr, out_b1, out_b2, out_o, E);
}